// round 1
// baseline (speedup 1.0000x reference)
#include <cuda_runtime.h>
#include <cstdint>

// ---------------------------------------------------------------------------
// SymmetricContraction: out[b,c] = W1*(u1.x) + sum_k W2_k * x^T U2_k x
//                                + sum_k W3_k * sum_{w,i,j} U3[w,i,j,k] x_w x_i x_j
// with W?[b,c,k] = sum_e y[b,e] * w?[e,k,c]
//
// Shapes: B=5888 (derived), C=128, L=16, E=10, P3=23, P2=4, P1=1
// ---------------------------------------------------------------------------

#define CC   128
#define LL   16
#define EE   10
#define PP3  23
#define PP2  4
#define NU3  (LL*LL*LL*PP3)   // 94208
#define NU2  (LL*LL*PP2)      // 1024

#define SMAX3 5888            // shared-memory cap for U3 entries (expect ~4710)
#define SMAX2 256             // shared-memory cap for U2 entries (expect ~51)

// device scratch (no allocation allowed)
__device__ uint2        g_ent3[NU3];
__device__ uint2        g_ent2[NU2];
__device__ unsigned int g_n3;
__device__ unsigned int g_n2;

// ---------------------------------------------------------------------------
// deterministic order-preserving compaction helper: exclusive scan over 1024
// ---------------------------------------------------------------------------
__device__ __forceinline__ int block_exscan_1024(int cnt, int t, int* warp_sums, int* total)
{
    __syncthreads();              // protect warp_sums reuse across calls
    const int lane = t & 31, wid = t >> 5;
    int inc = cnt;
#pragma unroll
    for (int d = 1; d < 32; d <<= 1) {
        int n = __shfl_up_sync(0xffffffffu, inc, d);
        if (lane >= d) inc += n;
    }
    if (lane == 31) warp_sums[wid] = inc;
    __syncthreads();
    if (wid == 0) {
        int v = warp_sums[lane];
#pragma unroll
        for (int d = 1; d < 32; d <<= 1) {
            int n = __shfl_up_sync(0xffffffffu, v, d);
            if (lane >= d) v += n;
        }
        warp_sums[lane] = v;      // inclusive sums of warp totals
    }
    __syncthreads();
    *total = warp_sums[31];
    return inc - cnt + (wid ? warp_sums[wid - 1] : 0);
}

// ---------------------------------------------------------------------------
// Preprocess: compact U3/U2 nonzeros into flagged sparse lists.
// Entry format: .x = k | (i<<8) | (x2<<12) | (w<<16) | (group_start ? 0x80000000 : 0)
//               .y = float bits of value
// Natural linear order of U3 (k fastest) groups entries by (w,x2,i).
// Each thread owns exactly 4 complete groups (92 = 4*23 elems) -> flags local.
// ---------------------------------------------------------------------------
__global__ __launch_bounds__(1024)
void build_sparse_kernel(const float* __restrict__ U3, const float* __restrict__ U2)
{
    __shared__ int warp_sums[32];
    const int t = threadIdx.x;

    // ---------------- U3 ----------------
    const int base = t * 92;
    int cnt = 0;
#pragma unroll
    for (int j = 0; j < 92; j += 4) {
        float4 v = *reinterpret_cast<const float4*>(U3 + base + j);
        cnt += (v.x != 0.f) + (v.y != 0.f) + (v.z != 0.f) + (v.w != 0.f);
    }
    int total3;
    int pos = block_exscan_1024(cnt, t, warp_sums, &total3);

#pragma unroll
    for (int g = 0; g < 4; ++g) {
        const int gbase = base + g * PP3;
        const int gid   = t * 4 + g;                 // group id = w*256 + x2*16 + i
        const uint32_t wxi = ((uint32_t)(gid & 15) << 8)
                           | ((uint32_t)((gid >> 4) & 15) << 12)
                           | ((uint32_t)((gid >> 8) & 15) << 16);
        bool first = true;
        for (int k = 0; k < PP3; ++k) {
            float v = U3[gbase + k];
            if (v != 0.f) {
                uint32_t idx = (uint32_t)k | wxi | (first ? 0x80000000u : 0u);
                g_ent3[pos] = make_uint2(idx, __float_as_uint(v));
                ++pos;
                first = false;
            }
        }
    }
    if (t == 0) g_n3 = (unsigned int)total3;

    // ---------------- U2 ----------------
    int cnt2 = 0;
    if (t < 256) {
        const int b2 = t * PP2;
#pragma unroll
        for (int k = 0; k < PP2; ++k) cnt2 += (U2[b2 + k] != 0.f);
    }
    int total2;
    int pos2 = block_exscan_1024(cnt2, t, warp_sums, &total2);
    if (t < 256) {
        const int b2 = t * PP2;
        const uint32_t wx = ((uint32_t)(t & 15) << 12) | ((uint32_t)(t >> 4) << 16);
        bool first = true;
        for (int k = 0; k < PP2; ++k) {
            float v = U2[b2 + k];
            if (v != 0.f) {
                uint32_t idx = (uint32_t)k | wx | (first ? 0x80000000u : 0u);
                g_ent2[pos2] = make_uint2(idx, __float_as_uint(v));
                ++pos2;
                first = false;
            }
        }
    }
    if (t == 0) g_n2 = (unsigned int)total2;
}

// ---------------------------------------------------------------------------
// Main kernel: 256 threads = 2 nodes x 128 channels. One thread per (b,c).
// Shared layout (dynamic):
//   esm  : uint2[SMAX3]          U3 entries (broadcast reads)
//   e2sm : uint2[SMAX2]          U2 entries
//   W3sm : float[23*256]         [k][tid] effective weights (conflict-free)
//   W2sm : float[4*256]
//   Xsm  : float[16*256]         [l][tid] node features
//   u1sm : float[16]
//   ysm  : float[32]             [sub][e]
// ---------------------------------------------------------------------------
#define SH_BYTES (SMAX3*8 + SMAX2*8 + (PP3+PP2+LL)*256*4 + 16*4 + 32*4)

__global__ __launch_bounds__(256)
void sym_contract_kernel(const float* __restrict__ x,
                         const float* __restrict__ y,
                         const float* __restrict__ w3,
                         const float* __restrict__ w2,
                         const float* __restrict__ w1,
                         const float* __restrict__ U1,
                         float* __restrict__ out,
                         int B)
{
    extern __shared__ unsigned char smem[];
    uint2* esm  = reinterpret_cast<uint2*>(smem);
    uint2* e2sm = reinterpret_cast<uint2*>(smem + SMAX3 * 8);
    float* W3sm = reinterpret_cast<float*>(smem + SMAX3 * 8 + SMAX2 * 8);
    float* W2sm = W3sm + PP3 * 256;
    float* Xsm  = W2sm + PP2 * 256;
    float* u1sm = Xsm + LL * 256;
    float* ysm  = u1sm + 16;

    const int tid = threadIdx.x;
    const int c   = tid & 127;
    const int sub = tid >> 7;
    const int b   = blockIdx.x * 2 + sub;
    const bool valid = (b < B);

    const int n3  = (int)g_n3;
    const int n2  = (int)g_n2;
    const int n3s = min(n3, SMAX3);
    const int n2s = min(n2, SMAX2);

    // stage sparse lists + small tensors
    for (int e = tid; e < n3s; e += 256) esm[e]  = g_ent3[e];
    for (int e = tid; e < n2s; e += 256) e2sm[e] = g_ent2[e];
    if (tid < 16) u1sm[tid] = U1[tid];
    if (tid < 2 * EE) {
        int e = tid % EE, s2 = tid / EE;
        int bb = blockIdx.x * 2 + s2;
        ysm[s2 * 16 + e] = (bb < B) ? y[bb * EE + e] : 0.f;
    }
    // node features -> Xsm[l][tid]
    if (valid) {
        const float4* xp4 = reinterpret_cast<const float4*>(x + (size_t)(b * CC + c) * LL);
#pragma unroll
        for (int q = 0; q < 4; ++q) {
            float4 v = xp4[q];
            Xsm[(q * 4 + 0) * 256 + tid] = v.x;
            Xsm[(q * 4 + 1) * 256 + tid] = v.y;
            Xsm[(q * 4 + 2) * 256 + tid] = v.z;
            Xsm[(q * 4 + 3) * 256 + tid] = v.w;
        }
    } else {
#pragma unroll
        for (int l = 0; l < LL; ++l) Xsm[l * 256 + tid] = 0.f;
    }
    __syncthreads();

    // effective weights W3[k], W2[k], W1 for this (b,c)
    float yr[EE];
#pragma unroll
    for (int e = 0; e < EE; ++e) yr[e] = ysm[sub * 16 + e];

#pragma unroll
    for (int k = 0; k < PP3; ++k) {
        float s = 0.f;
#pragma unroll
        for (int e = 0; e < EE; ++e) s = fmaf(yr[e], w3[(e * PP3 + k) * CC + c], s);
        W3sm[k * 256 + tid] = s;
    }
#pragma unroll
    for (int k = 0; k < PP2; ++k) {
        float s = 0.f;
#pragma unroll
        for (int e = 0; e < EE; ++e) s = fmaf(yr[e], w2[(e * PP2 + k) * CC + c], s);
        W2sm[k * 256 + tid] = s;
    }
    float W1 = 0.f;
#pragma unroll
    for (int e = 0; e < EE; ++e) W1 = fmaf(yr[e], w1[e * CC + c], W1);
    __syncthreads();

    float acc = 0.f;

    // ---- U3 contraction: grouped by (w,x2,i), k inner ----
    {
        float s = 0.f, xp = 0.f;
        for (int e = 0; e < n3s; ++e) {
            uint2 E = esm[e];
            if (E.x & 0x80000000u) {
                acc = fmaf(s, xp, acc);
                s  = 0.f;
                xp = Xsm[((E.x >> 16) & 15) * 256 + tid]
                   * Xsm[((E.x >> 12) & 15) * 256 + tid]
                   * Xsm[((E.x >>  8) & 15) * 256 + tid];
            }
            s = fmaf(__uint_as_float(E.y), W3sm[(E.x & 255u) * 256 + tid], s);
        }
        for (int e = n3s; e < n3; ++e) {   // overflow fallback (normally empty)
            uint2 E = __ldg(&g_ent3[e]);
            if (E.x & 0x80000000u) {
                acc = fmaf(s, xp, acc);
                s  = 0.f;
                xp = Xsm[((E.x >> 16) & 15) * 256 + tid]
                   * Xsm[((E.x >> 12) & 15) * 256 + tid]
                   * Xsm[((E.x >>  8) & 15) * 256 + tid];
            }
            s = fmaf(__uint_as_float(E.y), W3sm[(E.x & 255u) * 256 + tid], s);
        }
        acc = fmaf(s, xp, acc);
    }

    // ---- U2 contraction: grouped by (w,x2) ----
    {
        float s = 0.f, xp = 0.f;
        for (int e = 0; e < n2s; ++e) {
            uint2 E = e2sm[e];
            if (E.x & 0x80000000u) {
                acc = fmaf(s, xp, acc);
                s  = 0.f;
                xp = Xsm[((E.x >> 16) & 15) * 256 + tid]
                   * Xsm[((E.x >> 12) & 15) * 256 + tid];
            }
            s = fmaf(__uint_as_float(E.y), W2sm[(E.x & 255u) * 256 + tid], s);
        }
        for (int e = n2s; e < n2; ++e) {   // overflow fallback
            uint2 E = __ldg(&g_ent2[e]);
            if (E.x & 0x80000000u) {
                acc = fmaf(s, xp, acc);
                s  = 0.f;
                xp = Xsm[((E.x >> 16) & 15) * 256 + tid]
                   * Xsm[((E.x >> 12) & 15) * 256 + tid];
            }
            s = fmaf(__uint_as_float(E.y), W2sm[(E.x & 255u) * 256 + tid], s);
        }
        acc = fmaf(s, xp, acc);
    }

    // ---- U1 contraction ----
    {
        float d = 0.f;
#pragma unroll
        for (int w = 0; w < LL; ++w) d = fmaf(u1sm[w], Xsm[w * 256 + tid], d);
        acc = fmaf(W1, d, acc);
    }

    if (valid) out[b * CC + c] = acc;
}

// ---------------------------------------------------------------------------
extern "C" void kernel_launch(void* const* d_in, const int* in_sizes, int n_in,
                              void* d_out, int out_size)
{
    const float* x  = (const float*)d_in[0];   // [B,C,L]
    const float* y  = (const float*)d_in[1];   // [B,E]
    const float* U3 = (const float*)d_in[2];   // [16,16,16,23]
    const float* U2 = (const float*)d_in[3];   // [16,16,4]
    const float* U1 = (const float*)d_in[4];   // [16,1]
    const float* w3 = (const float*)d_in[5];   // [10,23,128]
    const float* w2 = (const float*)d_in[6];   // [10,4,128]
    const float* w1 = (const float*)d_in[7];   // [10,1,128]
    float* out = (float*)d_out;

    const int B = in_sizes[0] / (CC * LL);

    build_sparse_kernel<<<1, 1024>>>(U3, U2);

    cudaFuncSetAttribute(sym_contract_kernel,
                         cudaFuncAttributeMaxDynamicSharedMemorySize, SH_BYTES);
    const int grid = (B + 1) / 2;
    sym_contract_kernel<<<grid, 256, SH_BYTES>>>(x, y, w3, w2, w1, U1, out, B);
}

// round 2
// speedup vs baseline: 1.0193x; 1.0193x over previous
#include <cuda_runtime.h>
#include <cstdint>

// ---------------------------------------------------------------------------
// SymmetricContraction, sparse two-level grouped, V=4 channels/thread.
// out[b,c] = W1*(u1.x) + sum_k W2_k * x^T U2_k x + sum_k W3_k * sum U3 x x x
// Shapes: B=5888, C=128, L=16, E=10, P3=23, P2=4, P1=1
// ---------------------------------------------------------------------------

#define CC   128
#define LL   16
#define EE   10
#define PP3  23
#define PP2  4
#define NU3  (LL*LL*LL*PP3)   // 94208
#define NU2  (LL*LL*PP2)      // 1024
#define NODES 8               // nodes per block (256 thr, 4ch/thr)

// device scratch (no allocation allowed). +2 pad for prefetch overrun.
__device__ uint4        g_ent3[NU3 + 2];
__device__ uint4        g_ent2[NU2 + 2];
__device__ unsigned int g_n3;
__device__ unsigned int g_n2;

// ---------------------------------------------------------------------------
__device__ __forceinline__ int block_exscan_1024(int cnt, int t, int* warp_sums, int* total)
{
    __syncthreads();
    const int lane = t & 31, wid = t >> 5;
    int inc = cnt;
#pragma unroll
    for (int d = 1; d < 32; d <<= 1) {
        int n = __shfl_up_sync(0xffffffffu, inc, d);
        if (lane >= d) inc += n;
    }
    if (lane == 31) warp_sums[wid] = inc;
    __syncthreads();
    if (wid == 0) {
        int v = warp_sums[lane];
#pragma unroll
        for (int d = 1; d < 32; d <<= 1) {
            int n = __shfl_up_sync(0xffffffffu, v, d);
            if (lane >= d) v += n;
        }
        warp_sums[lane] = v;
    }
    __syncthreads();
    *total = warp_sums[31];
    return inc - cnt + (wid ? warp_sums[wid - 1] : 0);
}

// ---------------------------------------------------------------------------
// Preprocess. U3 entry (uint4):
//  .x = k*4096 | FI(bit30: i-group start) | FP(bit31: pair start)
//  .y = i*4096
//  .z = w*4096 | (x2*4096 << 16)
//  .w = float bits of value
// Linear order of U3 (k fastest) -> grouped by pair (w,x2), i-group inner.
// Thread t owns 92 elems = 4 complete i-groups; pair = threads 4p..4p+3.
// ---------------------------------------------------------------------------
__global__ __launch_bounds__(1024)
void build_sparse_kernel(const float* __restrict__ U3, const float* __restrict__ U2)
{
    __shared__ int warp_sums[32];
    const int t = threadIdx.x;
    const int lane = t & 31;

    // ---------------- U3 ----------------
    const int base = t * 92;
    int cnt = 0;
#pragma unroll
    for (int j = 0; j < 92; j += 4) {
        float4 v = *reinterpret_cast<const float4*>(U3 + base + j);
        cnt += (v.x != 0.f) + (v.y != 0.f) + (v.z != 0.f) + (v.w != 0.f);
    }
    int total3;
    int pos = block_exscan_1024(cnt, t, warp_sums, &total3);

    // is this thread the first in its 4-thread pair group with any nonzero?
    unsigned ball = __ballot_sync(0xffffffffu, cnt > 0);
    unsigned below = ball & ((1u << lane) - 1u) & (0xFu << (lane & ~3));
    bool fp_pending = (cnt > 0) && (below == 0u);

    const uint32_t w   = (uint32_t)(t >> 6) & 15u;       // pair = t>>2
    const uint32_t x2  = (uint32_t)(t >> 2) & 15u;
    const uint32_t wz  = (w * 4096u) | ((x2 * 4096u) << 16);

#pragma unroll
    for (int g = 0; g < 4; ++g) {
        const int gbase = base + g * PP3;
        const uint32_t i = (uint32_t)(4 * (t & 3) + g);
        bool fi = true;
        for (int k = 0; k < PP3; ++k) {
            float v = U3[gbase + k];
            if (v != 0.f) {
                uint32_t w0 = (uint32_t)k * 4096u
                            | (fi ? 0x40000000u : 0u)
                            | (fp_pending ? 0x80000000u : 0u);
                g_ent3[pos] = make_uint4(w0, i * 4096u, wz, __float_as_uint(v));
                ++pos; fi = false; fp_pending = false;
            }
        }
    }
    if (t == 0) g_n3 = (unsigned int)total3;

    // ---------------- U2 ----------------
    int cnt2 = 0;
    if (t < 256) {
        const int b2 = t * PP2;
#pragma unroll
        for (int k = 0; k < PP2; ++k) cnt2 += (U2[b2 + k] != 0.f);
    }
    int total2;
    int pos2 = block_exscan_1024(cnt2, t, warp_sums, &total2);
    if (t < 256) {
        const int b2 = t * PP2;
        const uint32_t w2i = (uint32_t)(t >> 4) * 4096u;
        const uint32_t x2i = (uint32_t)(t & 15) * 4096u;
        bool first = true;
        for (int k = 0; k < PP2; ++k) {
            float v = U2[b2 + k];
            if (v != 0.f) {
                uint32_t w0 = (uint32_t)k * 4096u | (first ? 0x80000000u : 0u);
                g_ent2[pos2] = make_uint4(w0, w2i, x2i, __float_as_uint(v));
                ++pos2; first = false;
            }
        }
    }
    if (t == 0) {
        g_n2 = (unsigned int)total2;
        // pad for prefetch overrun
        g_ent3[total3]     = make_uint4(0, 0, 0, 0);
        g_ent3[total3 + 1] = make_uint4(0, 0, 0, 0);
        g_ent2[total2]     = make_uint4(0, 0, 0, 0);
        g_ent2[total2 + 1] = make_uint4(0, 0, 0, 0);
    }
}

// ---------------------------------------------------------------------------
// Main kernel: 256 threads, each handles 4 consecutive channels of one node.
// Warp <-> node (32 lanes * 4 ch = 128 ch). 8 nodes per block.
// Shared: W3sm[23][1024], W2sm[4][1024], Xsm[16][1024]; row stride 4096 B.
// ---------------------------------------------------------------------------
#define SH_FLOATS ((PP3 + PP2 + LL) * 1024)
#define SH_BYTES  (SH_FLOATS * 4)

__device__ __forceinline__ float4 f4z() { return make_float4(0.f, 0.f, 0.f, 0.f); }
__device__ __forceinline__ float4 f4fma(float4 a, float4 b, float4 c) {
    return make_float4(fmaf(a.x, b.x, c.x), fmaf(a.y, b.y, c.y),
                       fmaf(a.z, b.z, c.z), fmaf(a.w, b.w, c.w));
}
__device__ __forceinline__ float4 f4fmas(float a, float4 b, float4 c) {
    return make_float4(fmaf(a, b.x, c.x), fmaf(a, b.y, c.y),
                       fmaf(a, b.z, c.z), fmaf(a, b.w, c.w));
}
__device__ __forceinline__ float4 f4mul(float4 a, float4 b) {
    return make_float4(a.x * b.x, a.y * b.y, a.z * b.z, a.w * b.w);
}

__global__ __launch_bounds__(256)
void sym_contract_kernel(const float* __restrict__ x,
                         const float* __restrict__ y,
                         const float* __restrict__ w3,
                         const float* __restrict__ w2,
                         const float* __restrict__ w1,
                         const float* __restrict__ U1,
                         float* __restrict__ out,
                         int B)
{
    extern __shared__ float sm[];
    float* W3sm = sm;                    // [23][1024]
    float* W2sm = W3sm + PP3 * 1024;     // [4][1024]
    float* Xsm  = W2sm + PP2 * 1024;     // [16][1024]

    const int tid  = threadIdx.x;
    const int lane = tid & 31;
    const int node = tid >> 5;
    const int b    = blockIdx.x * NODES + node;
    const bool valid = (b < B);
    const int c0   = lane * 4;

    // ---- stage x (transpose 4 rows of 16 -> 16 rows of 4) ----
    if (valid) {
        const float4* xp = reinterpret_cast<const float4*>(x + ((size_t)b * CC + c0) * LL);
#pragma unroll
        for (int q = 0; q < 4; ++q) {
            float4 r0 = xp[0 * 4 + q];
            float4 r1 = xp[1 * 4 + q];
            float4 r2 = xp[2 * 4 + q];
            float4 r3 = xp[3 * 4 + q];
            *reinterpret_cast<float4*>(&Xsm[(q * 4 + 0) * 1024 + tid * 4]) =
                make_float4(r0.x, r1.x, r2.x, r3.x);
            *reinterpret_cast<float4*>(&Xsm[(q * 4 + 1) * 1024 + tid * 4]) =
                make_float4(r0.y, r1.y, r2.y, r3.y);
            *reinterpret_cast<float4*>(&Xsm[(q * 4 + 2) * 1024 + tid * 4]) =
                make_float4(r0.z, r1.z, r2.z, r3.z);
            *reinterpret_cast<float4*>(&Xsm[(q * 4 + 3) * 1024 + tid * 4]) =
                make_float4(r0.w, r1.w, r2.w, r3.w);
        }
    } else {
#pragma unroll
        for (int l = 0; l < LL; ++l)
            *reinterpret_cast<float4*>(&Xsm[l * 1024 + tid * 4]) = f4z();
    }

    // ---- effective weights ----
    float yr[EE];
#pragma unroll
    for (int e = 0; e < EE; ++e) yr[e] = valid ? __ldg(y + (size_t)b * EE + e) : 0.f;

#pragma unroll
    for (int k = 0; k < PP3; ++k) {
        float4 a = f4z();
#pragma unroll
        for (int e = 0; e < EE; ++e) {
            float4 wv = *reinterpret_cast<const float4*>(w3 + (size_t)(e * PP3 + k) * CC + c0);
            a = f4fmas(yr[e], wv, a);
        }
        *reinterpret_cast<float4*>(&W3sm[k * 1024 + tid * 4]) = a;
    }
#pragma unroll
    for (int k = 0; k < PP2; ++k) {
        float4 a = f4z();
#pragma unroll
        for (int e = 0; e < EE; ++e) {
            float4 wv = *reinterpret_cast<const float4*>(w2 + (size_t)(e * PP2 + k) * CC + c0);
            a = f4fmas(yr[e], wv, a);
        }
        *reinterpret_cast<float4*>(&W2sm[k * 1024 + tid * 4]) = a;
    }
    float4 W1r = f4z();
#pragma unroll
    for (int e = 0; e < EE; ++e) {
        float4 wv = *reinterpret_cast<const float4*>(w1 + (size_t)e * CC + c0);
        W1r = f4fmas(yr[e], wv, W1r);
    }
    __syncthreads();

    const int n3 = (int)g_n3;
    const int n2 = (int)g_n2;

    const char* W3b = reinterpret_cast<const char*>(W3sm) + tid * 16;
    const char* W2b = reinterpret_cast<const char*>(W2sm) + tid * 16;
    const char* Xb  = reinterpret_cast<const char*>(Xsm)  + tid * 16;

    float4 acc = f4z();

    // ---- U3: pair-outer / i-group / k-inner flagged stream ----
    if (n3 > 0) {
        float4 accp = f4z(), s = f4z(), xp2 = f4z(), xi = f4z();
        uint4 E  = __ldg(&g_ent3[0]);
        uint4 E1 = __ldg(&g_ent3[1]);
        for (int e = 0; e < n3; ++e) {
            uint4 En = __ldg(&g_ent3[e + 2]);   // padded, safe
            if (E.x & 0x40000000u) {            // i-group start
                accp = f4fma(xi, s, accp);
                s = f4z();
                if (E.x & 0x80000000u) {        // pair start
                    acc  = f4fma(xp2, accp, acc);
                    accp = f4z();
                    float4 xw = *reinterpret_cast<const float4*>(Xb + (E.z & 0xFFFFu));
                    float4 xx = *reinterpret_cast<const float4*>(Xb + (E.z >> 16));
                    xp2 = f4mul(xw, xx);
                }
                xi = *reinterpret_cast<const float4*>(Xb + E.y);
            }
            float4 wk = *reinterpret_cast<const float4*>(W3b + (E.x & 0x1FFFFu));
            s = f4fmas(__uint_as_float(E.w), wk, s);
            E = E1; E1 = En;
        }
        accp = f4fma(xi, s, accp);
        acc  = f4fma(xp2, accp, acc);
    }

    // ---- U2: single-level flagged stream ----
    if (n2 > 0) {
        float4 s2 = f4z(), xpp = f4z();
        for (int e = 0; e < n2; ++e) {
            uint4 E = __ldg(&g_ent2[e]);
            if (E.x & 0x80000000u) {
                acc = f4fma(xpp, s2, acc);
                s2 = f4z();
                float4 xw = *reinterpret_cast<const float4*>(Xb + E.y);
                float4 xx = *reinterpret_cast<const float4*>(Xb + E.z);
                xpp = f4mul(xw, xx);
            }
            float4 wk = *reinterpret_cast<const float4*>(W2b + (E.x & 0x1FFFFu));
            s2 = f4fmas(__uint_as_float(E.w), wk, s2);
        }
        acc = f4fma(xpp, s2, acc);
    }

    // ---- U1 ----
    {
        float4 d = f4z();
#pragma unroll
        for (int l = 0; l < LL; ++l) {
            float4 xv = *reinterpret_cast<const float4*>(Xb + l * 4096);
            d = f4fmas(__ldg(U1 + l), xv, d);
        }
        acc = f4fma(W1r, d, acc);
    }

    if (valid)
        *reinterpret_cast<float4*>(out + (size_t)b * CC + c0) = acc;
}

// ---------------------------------------------------------------------------
extern "C" void kernel_launch(void* const* d_in, const int* in_sizes, int n_in,
                              void* d_out, int out_size)
{
    const float* x  = (const float*)d_in[0];   // [B,C,L]
    const float* y  = (const float*)d_in[1];   // [B,E]
    const float* U3 = (const float*)d_in[2];   // [16,16,16,23]
    const float* U2 = (const float*)d_in[3];   // [16,16,4]
    const float* U1 = (const float*)d_in[4];   // [16,1]
    const float* w3 = (const float*)d_in[5];   // [10,23,128]
    const float* w2 = (const float*)d_in[6];   // [10,4,128]
    const float* w1 = (const float*)d_in[7];   // [10,1,128]
    float* out = (float*)d_out;

    const int B = in_sizes[0] / (CC * LL);

    build_sparse_kernel<<<1, 1024>>>(U3, U2);

    cudaFuncSetAttribute(sym_contract_kernel,
                         cudaFuncAttributeMaxDynamicSharedMemorySize, SH_BYTES);
    const int grid = (B + NODES - 1) / NODES;
    sym_contract_kernel<<<grid, 256, SH_BYTES>>>(x, y, w3, w2, w1, U1, out, B);
}

// round 3
// speedup vs baseline: 1.7855x; 1.7516x over previous
#include <cuda_runtime.h>
#include <cuda_fp16.h>
#include <cstdint>

// ---------------------------------------------------------------------------
// SymmetricContraction. out[b,c] = W1*(u1.x) + sum_k W2_k x^T U2_k x
//                                + sum_k W3_k sum U3 x x x
// B=5888, C=128, L=16, E=10, P3=23, P2=4, P1=1
// Branchless fixed-size-2-entry groups; W3/W2 as fp16 in smem; V=4 ch/thread.
// ---------------------------------------------------------------------------

#define CC    128
#define LL    16
#define EE    10
#define PP3   23
#define PP2   4
#define NODES 7                    // nodes per block (224 threads, warp=node)
#define CPB   (NODES*CC)           // 896 channels per block
#define XROW  (CPB*4)              // 3584 B : fp32 X row stride
#define W3R   (CPB*2)              // 1792 B : fp16 W row stride

#define NG3MAX (4096*12 + 8)       // worst-case packed U3 groups
#define NG2MAX (512 + 8)

// device scratch (no allocation allowed)
__device__ uint4        g_ent3[NG3MAX];
__device__ uint4        g_ent2[NG2MAX];
__device__ unsigned int g_pair3[260];
__device__ unsigned int g_n3g;
__device__ unsigned int g_n2g;

// ---------------------------------------------------------------------------
__device__ __forceinline__ int block_exscan_1024(int cnt, int t, int* warp_sums, int* total)
{
    __syncthreads();
    const int lane = t & 31, wid = t >> 5;
    int inc = cnt;
#pragma unroll
    for (int d = 1; d < 32; d <<= 1) {
        int n = __shfl_up_sync(0xffffffffu, inc, d);
        if (lane >= d) inc += n;
    }
    if (lane == 31) warp_sums[wid] = inc;
    __syncthreads();
    if (wid == 0) {
        int v = warp_sums[lane];
#pragma unroll
        for (int d = 1; d < 32; d <<= 1) {
            int n = __shfl_up_sync(0xffffffffu, v, d);
            if (lane >= d) v += n;
        }
        warp_sums[lane] = v;
    }
    __syncthreads();
    *total = warp_sums[31];
    return inc - cnt + (wid ? warp_sums[wid - 1] : 0);
}

// ---------------------------------------------------------------------------
// Build packed streams.
// U3 group (uint4): .x = i_byte_off(16b) | pairStart<<31
//                   .y = v1 (f32 bits)   .z = v2 (f32 bits, 0 if padded)
//                   .w = k1_byte_off(16b) | k2_byte_off<<16
// Pair record (uint): w_off(16b) | x_off<<16   (consumed in stream order)
// Thread t owns i-groups gid = t*4+g ; pair = t>>2 ; quad = 4 threads.
// ---------------------------------------------------------------------------
__global__ __launch_bounds__(1024)
void build_sparse_kernel(const float* __restrict__ U3, const float* __restrict__ U2)
{
    __shared__ int warp_sums[32];
    const int t = threadIdx.x;
    const int lane = t & 31;

    // ---- U3: count packed groups ----
    const int base = t * 92;
    int emit_cnt = 0;
#pragma unroll
    for (int g = 0; g < 4; ++g) {
        int c = 0;
        for (int k = 0; k < PP3; ++k) c += (U3[base + g * PP3 + k] != 0.f);
        emit_cnt += (c + 1) >> 1;
    }
    int total3;
    int gpos = block_exscan_1024(emit_cnt, t, warp_sums, &total3);

    unsigned ball  = __ballot_sync(0xffffffffu, emit_cnt > 0);
    unsigned below = ball & ((1u << lane) - 1u) & (0xFu << (lane & ~3));
    bool fp = (emit_cnt > 0) && (below == 0u);

    // ---- U3: emit ----
    for (int g = 0; g < 4; ++g) {
        const int gbase = base + g * PP3;
        const uint32_t i_off = (uint32_t)((t & 3) * 4 + g) * XROW;
        int k1 = 0; float v1 = 0.f; bool pending = false;
        for (int k = 0; k < PP3; ++k) {
            float v = U3[gbase + k];
            if (v != 0.f) {
                if (!pending) { k1 = k; v1 = v; pending = true; }
                else {
                    g_ent3[gpos++] = make_uint4(i_off | (fp ? 0x80000000u : 0u),
                                                __float_as_uint(v1), __float_as_uint(v),
                                                (uint32_t)k1 * W3R | ((uint32_t)k * W3R << 16));
                    fp = false; pending = false;
                }
            }
        }
        if (pending) {
            g_ent3[gpos++] = make_uint4(i_off | (fp ? 0x80000000u : 0u),
                                        __float_as_uint(v1), 0u,
                                        (uint32_t)k1 * W3R);
            fp = false;
        }
    }

    // ---- pair records (in pair order) ----
    bool leader   = ((t & 3) == 0);
    bool quad_any = (((ball >> (lane & ~3)) & 0xFu) != 0u);
    int totalp;
    int ppos = block_exscan_1024((leader && quad_any) ? 1 : 0, t, warp_sums, &totalp);
    if (leader && quad_any) {
        uint32_t w  = (uint32_t)(t >> 6);
        uint32_t x2 = (uint32_t)(t >> 2) & 15u;
        g_pair3[ppos] = (w * XROW) | ((x2 * XROW) << 16);
    }

    // ---- U2: packed groups, pair offsets embedded, no flags ----
    int emit2 = 0;
    if (t < 256) {
        int c = 0;
#pragma unroll
        for (int k = 0; k < PP2; ++k) c += (U2[t * PP2 + k] != 0.f);
        emit2 = (c + 1) >> 1;
    }
    int total2;
    int p2 = block_exscan_1024(emit2, t, warp_sums, &total2);
    if (t < 256) {
        const uint32_t wx = ((uint32_t)(t >> 4) * XROW) | (((uint32_t)(t & 15) * XROW) << 16);
        int k1 = 0; float v1 = 0.f; bool pending = false;
        for (int k = 0; k < PP2; ++k) {
            float v = U2[t * PP2 + k];
            if (v != 0.f) {
                if (!pending) { k1 = k; v1 = v; pending = true; }
                else {
                    g_ent2[p2++] = make_uint4(wx, __float_as_uint(v1), __float_as_uint(v),
                                              (uint32_t)k1 * W3R | ((uint32_t)k * W3R << 16));
                    pending = false;
                }
            }
        }
        if (pending)
            g_ent2[p2++] = make_uint4(wx, __float_as_uint(v1), 0u, (uint32_t)k1 * W3R);
    }

    if (t == 0) {
        int pad3 = (total3 + 3) & ~3;            // pad for unroll-4
        for (int j = total3; j < pad3; ++j) g_ent3[j] = make_uint4(0, 0, 0, 0);
        g_n3g = (unsigned)pad3;
        g_n2g = (unsigned)total2;
    }
}

// ---------------------------------------------------------------------------
__device__ __forceinline__ float4 f4z() { return make_float4(0.f, 0.f, 0.f, 0.f); }
__device__ __forceinline__ float4 f4fma(float4 a, float4 b, float4 c) {
    return make_float4(fmaf(a.x, b.x, c.x), fmaf(a.y, b.y, c.y),
                       fmaf(a.z, b.z, c.z), fmaf(a.w, b.w, c.w));
}
__device__ __forceinline__ float4 f4fmas(float a, float4 b, float4 c) {
    return make_float4(fmaf(a, b.x, c.x), fmaf(a, b.y, c.y),
                       fmaf(a, b.z, c.z), fmaf(a, b.w, c.w));
}
__device__ __forceinline__ float4 f4muls(float a, float4 b) {
    return make_float4(a * b.x, a * b.y, a * b.z, a * b.w);
}
__device__ __forceinline__ float4 f4mul(float4 a, float4 b) {
    return make_float4(a.x * b.x, a.y * b.y, a.z * b.z, a.w * b.w);
}
__device__ __forceinline__ float4 h4_to_f4(uint2 u) {
    float2 a = __half22float2(*reinterpret_cast<__half2*>(&u.x));
    float2 b = __half22float2(*reinterpret_cast<__half2*>(&u.y));
    return make_float4(a.x, a.y, b.x, b.y);
}
__device__ __forceinline__ void st_h4(void* p, float4 a) {
    uint2 u;
    *reinterpret_cast<__half2*>(&u.x) = __float22half2_rn(make_float2(a.x, a.y));
    *reinterpret_cast<__half2*>(&u.y) = __float22half2_rn(make_float2(a.z, a.w));
    *reinterpret_cast<uint2*>(p) = u;
}

// smem: Xs fp32 [16][896] | W3h fp16 [23][896] | W2h fp16 [4][896]
#define SM_X   0
#define SM_W3  (16*CPB*4)                 // 57344
#define SM_W2  (SM_W3 + PP3*CPB*2)        // +41216
#define SH_BYTES (SM_W2 + PP2*CPB*2)      // 105728

__global__ __launch_bounds__(NODES*32, 2)
void sym_contract_kernel(const float* __restrict__ x,
                         const float* __restrict__ y,
                         const float* __restrict__ w3,
                         const float* __restrict__ w2,
                         const float* __restrict__ w1,
                         const float* __restrict__ U1,
                         float* __restrict__ out,
                         int B)
{
    extern __shared__ char sm[];
    float* Xs  = reinterpret_cast<float*>(sm + SM_X);
    char*  W3h = sm + SM_W3;
    char*  W2h = sm + SM_W2;

    const int tid  = threadIdx.x;
    const int lane = tid & 31;
    const int node = tid >> 5;
    const int b    = blockIdx.x * NODES + node;
    const bool valid = (b < B);
    const int c0   = lane * 4;
    const int colf = node * CC + c0;          // float column base
    float* Xcol = Xs + colf;

    // ---- stage x (transpose 4 channels x 16 -> rows) ----
    if (valid) {
        const float4* xp = reinterpret_cast<const float4*>(x + ((size_t)b * CC + c0) * LL);
#pragma unroll
        for (int q = 0; q < 4; ++q) {
            float4 r0 = xp[0 * 4 + q], r1 = xp[1 * 4 + q];
            float4 r2 = xp[2 * 4 + q], r3 = xp[3 * 4 + q];
            *reinterpret_cast<float4*>(Xcol + (q * 4 + 0) * CPB) = make_float4(r0.x, r1.x, r2.x, r3.x);
            *reinterpret_cast<float4*>(Xcol + (q * 4 + 1) * CPB) = make_float4(r0.y, r1.y, r2.y, r3.y);
            *reinterpret_cast<float4*>(Xcol + (q * 4 + 2) * CPB) = make_float4(r0.z, r1.z, r2.z, r3.z);
            *reinterpret_cast<float4*>(Xcol + (q * 4 + 3) * CPB) = make_float4(r0.w, r1.w, r2.w, r3.w);
        }
    } else {
#pragma unroll
        for (int l = 0; l < LL; ++l)
            *reinterpret_cast<float4*>(Xcol + l * CPB) = f4z();
    }

    // ---- effective weights (fp16 storage) ----
    float yr[EE];
#pragma unroll
    for (int e = 0; e < EE; ++e) yr[e] = valid ? __ldg(y + (size_t)b * EE + e) : 0.f;

#pragma unroll
    for (int k = 0; k < PP3; ++k) {
        float4 a = f4z();
#pragma unroll
        for (int e = 0; e < EE; ++e) {
            float4 wv = *reinterpret_cast<const float4*>(w3 + (size_t)(e * PP3 + k) * CC + c0);
            a = f4fmas(yr[e], wv, a);
        }
        st_h4(W3h + k * W3R + colf * 2, a);
    }
#pragma unroll
    for (int k = 0; k < PP2; ++k) {
        float4 a = f4z();
#pragma unroll
        for (int e = 0; e < EE; ++e) {
            float4 wv = *reinterpret_cast<const float4*>(w2 + (size_t)(e * PP2 + k) * CC + c0);
            a = f4fmas(yr[e], wv, a);
        }
        st_h4(W2h + k * W3R + colf * 2, a);
    }
    float4 W1r = f4z();
#pragma unroll
    for (int e = 0; e < EE; ++e) {
        float4 wv = *reinterpret_cast<const float4*>(w1 + (size_t)e * CC + c0);
        W1r = f4fmas(yr[e], wv, W1r);
    }
    __syncwarp();   // smem columns are thread-private; ordering only

    const int n3g = (int)g_n3g;
    const int n2g = (int)g_n2g;

    const char* Xb  = reinterpret_cast<const char*>(Xs) + colf * 4;
    const char* W3b = W3h + colf * 2;
    const char* W2b = W2h + colf * 2;

    float4 acc = f4z();

    // ---- U3: branchless fixed-2 groups; rare pair-start branch ----
    {
        float4 accp = f4z(), xp = f4z();
        int pp = 0;
#pragma unroll 4
        for (int e = 0; e < n3g; ++e) {
            uint4 E = __ldg(&g_ent3[e]);
            if (E.x & 0x80000000u) {                 // pair start (~8%)
                acc  = f4fma(xp, accp, acc);
                accp = f4z();
                unsigned P = __ldg(&g_pair3[pp++]);
                float4 xw = *reinterpret_cast<const float4*>(Xb + (P & 0xffffu));
                float4 xx = *reinterpret_cast<const float4*>(Xb + (P >> 16));
                xp = f4mul(xw, xx);
            }
            float4 xi = *reinterpret_cast<const float4*>(Xb + (E.x & 0xffffu));
            float4 wa = h4_to_f4(*reinterpret_cast<const uint2*>(W3b + (E.w & 0xffffu)));
            float4 wb = h4_to_f4(*reinterpret_cast<const uint2*>(W3b + (E.w >> 16)));
            float4 s  = f4muls(__uint_as_float(E.y), wa);
            s = f4fmas(__uint_as_float(E.z), wb, s);
            accp = f4fma(xi, s, accp);
        }
        acc = f4fma(xp, accp, acc);
    }

    // ---- U2: self-contained groups ----
    for (int e = 0; e < n2g; ++e) {
        uint4 E = __ldg(&g_ent2[e]);
        float4 xw = *reinterpret_cast<const float4*>(Xb + (E.x & 0xffffu));
        float4 xx = *reinterpret_cast<const float4*>(Xb + (E.x >> 16));
        float4 wa = h4_to_f4(*reinterpret_cast<const uint2*>(W2b + (E.w & 0xffffu)));
        float4 wb = h4_to_f4(*reinterpret_cast<const uint2*>(W2b + (E.w >> 16)));
        float4 s  = f4muls(__uint_as_float(E.y), wa);
        s = f4fmas(__uint_as_float(E.z), wb, s);
        acc = f4fma(f4mul(xw, xx), s, acc);
    }

    // ---- U1 ----
    {
        float4 d = f4z();
#pragma unroll
        for (int l = 0; l < LL; ++l) {
            float4 xv = *reinterpret_cast<const float4*>(Xb + l * XROW);
            d = f4fmas(__ldg(U1 + l), xv, d);
        }
        acc = f4fma(W1r, d, acc);
    }

    if (valid)
        *reinterpret_cast<float4*>(out + (size_t)b * CC + c0) = acc;
}

// ---------------------------------------------------------------------------
extern "C" void kernel_launch(void* const* d_in, const int* in_sizes, int n_in,
                              void* d_out, int out_size)
{
    const float* x  = (const float*)d_in[0];   // [B,C,L]
    const float* y  = (const float*)d_in[1];   // [B,E]
    const float* U3 = (const float*)d_in[2];   // [16,16,16,23]
    const float* U2 = (const float*)d_in[3];   // [16,16,4]
    const float* U1 = (const float*)d_in[4];   // [16,1]
    const float* w3 = (const float*)d_in[5];   // [10,23,128]
    const float* w2 = (const float*)d_in[6];   // [10,4,128]
    const float* w1 = (const float*)d_in[7];   // [10,1,128]
    float* out = (float*)d_out;

    const int B = in_sizes[0] / (CC * LL);

    build_sparse_kernel<<<1, 1024>>>(U3, U2);

    cudaFuncSetAttribute(sym_contract_kernel,
                         cudaFuncAttributeMaxDynamicSharedMemorySize, SH_BYTES);
    const int grid = (B + NODES - 1) / NODES;
    sym_contract_kernel<<<grid, NODES * 32, SH_BYTES>>>(x, y, w3, w2, w1, U1, out, B);
}

// round 4
// speedup vs baseline: 1.9672x; 1.1018x over previous
#include <cuda_runtime.h>
#include <cuda_fp16.h>
#include <cstdint>

// ---------------------------------------------------------------------------
// SymmetricContraction. out[b,c] = W1*(u1.x) + sum_k W2_k x^T U2_k x
//                                + sum_k W3_k sum U3 x x x
// B=5888, C=128, L=16, E=10, P3=23, P2=4, P1=1
// Fixed-2-entry groups; X and W stored fp16 in smem; fp32 accumulate.
// ---------------------------------------------------------------------------

#define CC    128
#define LL    16
#define EE    10
#define PP3   23
#define PP2   4
#define NODES 9                    // nodes per block (288 threads, warp=node)
#define CPB   (NODES*CC)           // 1152 channels per block
#define XROW  (CPB*2)              // 2304 B : fp16 X row stride
#define W3R   (CPB*2)              // 2304 B : fp16 W row stride

#define NG3MAX (4096*12 + 8)
#define NG2MAX (512 + 8)

// device scratch (no allocation allowed)
__device__ uint4        g_ent3[NG3MAX];
__device__ uint4        g_ent2[NG2MAX];
__device__ unsigned int g_pair3[260];
__device__ unsigned int g_n3g;
__device__ unsigned int g_n2g;

// ---------------------------------------------------------------------------
__device__ __forceinline__ int block_exscan_1024(int cnt, int t, int* warp_sums, int* total)
{
    __syncthreads();
    const int lane = t & 31, wid = t >> 5;
    int inc = cnt;
#pragma unroll
    for (int d = 1; d < 32; d <<= 1) {
        int n = __shfl_up_sync(0xffffffffu, inc, d);
        if (lane >= d) inc += n;
    }
    if (lane == 31) warp_sums[wid] = inc;
    __syncthreads();
    if (wid == 0) {
        int v = warp_sums[lane];
#pragma unroll
        for (int d = 1; d < 32; d <<= 1) {
            int n = __shfl_up_sync(0xffffffffu, v, d);
            if (lane >= d) v += n;
        }
        warp_sums[lane] = v;
    }
    __syncthreads();
    *total = warp_sums[31];
    return inc - cnt + (wid ? warp_sums[wid - 1] : 0);
}

// ---------------------------------------------------------------------------
// U3 group (uint4): .x = i_byte_off(16b) | pairStart<<31
//                   .y = v1 (f32 bits)   .z = v2 (f32 bits, 0 if padded)
//                   .w = k1_byte_off(16b) | k2_byte_off<<16
// Pair record (uint): w_off(16b) | x_off<<16  (consumed in stream order)
// ---------------------------------------------------------------------------
__global__ __launch_bounds__(1024)
void build_sparse_kernel(const float* __restrict__ U3, const float* __restrict__ U2)
{
    __shared__ int warp_sums[32];
    const int t = threadIdx.x;
    const int lane = t & 31;

    const int base = t * 92;
    int emit_cnt = 0;
#pragma unroll
    for (int g = 0; g < 4; ++g) {
        int c = 0;
        for (int k = 0; k < PP3; ++k) c += (U3[base + g * PP3 + k] != 0.f);
        emit_cnt += (c + 1) >> 1;
    }
    int total3;
    int gpos = block_exscan_1024(emit_cnt, t, warp_sums, &total3);

    unsigned ball  = __ballot_sync(0xffffffffu, emit_cnt > 0);
    unsigned below = ball & ((1u << lane) - 1u) & (0xFu << (lane & ~3));
    bool fp = (emit_cnt > 0) && (below == 0u);

    for (int g = 0; g < 4; ++g) {
        const int gbase = base + g * PP3;
        const uint32_t i_off = (uint32_t)((t & 3) * 4 + g) * XROW;
        int k1 = 0; float v1 = 0.f; bool pending = false;
        for (int k = 0; k < PP3; ++k) {
            float v = U3[gbase + k];
            if (v != 0.f) {
                if (!pending) { k1 = k; v1 = v; pending = true; }
                else {
                    g_ent3[gpos++] = make_uint4(i_off | (fp ? 0x80000000u : 0u),
                                                __float_as_uint(v1), __float_as_uint(v),
                                                (uint32_t)k1 * W3R | ((uint32_t)k * W3R << 16));
                    fp = false; pending = false;
                }
            }
        }
        if (pending) {
            g_ent3[gpos++] = make_uint4(i_off | (fp ? 0x80000000u : 0u),
                                        __float_as_uint(v1), 0u,
                                        (uint32_t)k1 * W3R);
            fp = false;
        }
    }

    bool leader   = ((t & 3) == 0);
    bool quad_any = (((ball >> (lane & ~3)) & 0xFu) != 0u);
    int totalp;
    int ppos = block_exscan_1024((leader && quad_any) ? 1 : 0, t, warp_sums, &totalp);
    if (leader && quad_any) {
        uint32_t w  = (uint32_t)(t >> 6);
        uint32_t x2 = (uint32_t)(t >> 2) & 15u;
        g_pair3[ppos] = (w * XROW) | ((x2 * XROW) << 16);
    }

    int emit2 = 0;
    if (t < 256) {
        int c = 0;
#pragma unroll
        for (int k = 0; k < PP2; ++k) c += (U2[t * PP2 + k] != 0.f);
        emit2 = (c + 1) >> 1;
    }
    int total2;
    int p2 = block_exscan_1024(emit2, t, warp_sums, &total2);
    if (t < 256) {
        const uint32_t wx = ((uint32_t)(t >> 4) * XROW) | (((uint32_t)(t & 15) * XROW) << 16);
        int k1 = 0; float v1 = 0.f; bool pending = false;
        for (int k = 0; k < PP2; ++k) {
            float v = U2[t * PP2 + k];
            if (v != 0.f) {
                if (!pending) { k1 = k; v1 = v; pending = true; }
                else {
                    g_ent2[p2++] = make_uint4(wx, __float_as_uint(v1), __float_as_uint(v),
                                              (uint32_t)k1 * W3R | ((uint32_t)k * W3R << 16));
                    pending = false;
                }
            }
        }
        if (pending)
            g_ent2[p2++] = make_uint4(wx, __float_as_uint(v1), 0u, (uint32_t)k1 * W3R);
    }

    if (t == 0) {
        int pad3 = (total3 + 3) & ~3;
        for (int j = total3; j < pad3; ++j) g_ent3[j] = make_uint4(0, 0, 0, 0);
        g_n3g = (unsigned)pad3;
        g_n2g = (unsigned)total2;
    }
}

// ---------------------------------------------------------------------------
__device__ __forceinline__ float4 f4z() { return make_float4(0.f, 0.f, 0.f, 0.f); }
__device__ __forceinline__ float4 f4fma(float4 a, float4 b, float4 c) {
    return make_float4(fmaf(a.x, b.x, c.x), fmaf(a.y, b.y, c.y),
                       fmaf(a.z, b.z, c.z), fmaf(a.w, b.w, c.w));
}
__device__ __forceinline__ float4 f4fmas(float a, float4 b, float4 c) {
    return make_float4(fmaf(a, b.x, c.x), fmaf(a, b.y, c.y),
                       fmaf(a, b.z, c.z), fmaf(a, b.w, c.w));
}
__device__ __forceinline__ float4 f4muls(float a, float4 b) {
    return make_float4(a * b.x, a * b.y, a * b.z, a * b.w);
}
__device__ __forceinline__ float4 f4mul(float4 a, float4 b) {
    return make_float4(a.x * b.x, a.y * b.y, a.z * b.z, a.w * b.w);
}
__device__ __forceinline__ float4 h4_to_f4(uint2 u) {
    float2 a = __half22float2(*reinterpret_cast<__half2*>(&u.x));
    float2 b = __half22float2(*reinterpret_cast<__half2*>(&u.y));
    return make_float4(a.x, a.y, b.x, b.y);
}
__device__ __forceinline__ uint2 f4_to_h4(float4 a) {
    uint2 u;
    *reinterpret_cast<__half2*>(&u.x) = __float22half2_rn(make_float2(a.x, a.y));
    *reinterpret_cast<__half2*>(&u.y) = __float22half2_rn(make_float2(a.z, a.w));
    return u;
}

// smem: Xh fp16 [16][1152] | W3h fp16 [23][1152] | W2h fp16 [4][1152]
#define SM_X   0
#define SM_W3  (LL*CPB*2)                  // 36864
#define SM_W2  (SM_W3 + PP3*CPB*2)         // +52992
#define SH_BYTES (SM_W2 + PP2*CPB*2)       // 99072

__global__ __launch_bounds__(NODES*32, 2)
void sym_contract_kernel(const float* __restrict__ x,
                         const float* __restrict__ y,
                         const float* __restrict__ w3,
                         const float* __restrict__ w2,
                         const float* __restrict__ w1,
                         const float* __restrict__ U1,
                         float* __restrict__ out,
                         int B)
{
    extern __shared__ char sm[];
    char* Xh  = sm + SM_X;
    char* W3h = sm + SM_W3;
    char* W2h = sm + SM_W2;

    const int tid  = threadIdx.x;
    const int lane = tid & 31;
    const int node = tid >> 5;
    const int b    = blockIdx.x * NODES + node;
    const bool valid = (b < B);
    const int c0   = lane * 4;
    const int colf = node * CC + c0;          // channel column base within block

    // ---- stage x (fp16 rows) ----
    if (valid) {
        const float4* xp = reinterpret_cast<const float4*>(x + ((size_t)b * CC + c0) * LL);
#pragma unroll
        for (int q = 0; q < 4; ++q) {
            float4 r0 = xp[0 * 4 + q], r1 = xp[1 * 4 + q];
            float4 r2 = xp[2 * 4 + q], r3 = xp[3 * 4 + q];
            *reinterpret_cast<uint2*>(Xh + (q * 4 + 0) * XROW + colf * 2) =
                f4_to_h4(make_float4(r0.x, r1.x, r2.x, r3.x));
            *reinterpret_cast<uint2*>(Xh + (q * 4 + 1) * XROW + colf * 2) =
                f4_to_h4(make_float4(r0.y, r1.y, r2.y, r3.y));
            *reinterpret_cast<uint2*>(Xh + (q * 4 + 2) * XROW + colf * 2) =
                f4_to_h4(make_float4(r0.z, r1.z, r2.z, r3.z));
            *reinterpret_cast<uint2*>(Xh + (q * 4 + 3) * XROW + colf * 2) =
                f4_to_h4(make_float4(r0.w, r1.w, r2.w, r3.w));
        }
    } else {
#pragma unroll
        for (int l = 0; l < LL; ++l)
            *reinterpret_cast<uint2*>(Xh + l * XROW + colf * 2) = make_uint2(0, 0);
    }

    // ---- effective weights (fp16 storage) ----
    float yr[EE];
#pragma unroll
    for (int e = 0; e < EE; ++e) yr[e] = valid ? __ldg(y + (size_t)b * EE + e) : 0.f;

#pragma unroll
    for (int k = 0; k < PP3; ++k) {
        float4 a = f4z();
#pragma unroll
        for (int e = 0; e < EE; ++e) {
            float4 wv = *reinterpret_cast<const float4*>(w3 + (size_t)(e * PP3 + k) * CC + c0);
            a = f4fmas(yr[e], wv, a);
        }
        *reinterpret_cast<uint2*>(W3h + k * W3R + colf * 2) = f4_to_h4(a);
    }
#pragma unroll
    for (int k = 0; k < PP2; ++k) {
        float4 a = f4z();
#pragma unroll
        for (int e = 0; e < EE; ++e) {
            float4 wv = *reinterpret_cast<const float4*>(w2 + (size_t)(e * PP2 + k) * CC + c0);
            a = f4fmas(yr[e], wv, a);
        }
        *reinterpret_cast<uint2*>(W2h + k * W3R + colf * 2) = f4_to_h4(a);
    }
    float4 W1r = f4z();
#pragma unroll
    for (int e = 0; e < EE; ++e) {
        float4 wv = *reinterpret_cast<const float4*>(w1 + (size_t)e * CC + c0);
        W1r = f4fmas(yr[e], wv, W1r);
    }
    __syncwarp();   // smem columns are thread-private; ordering only

    const int n3g = (int)g_n3g;
    const int n2g = (int)g_n2g;

    const char* Xb  = Xh  + colf * 2;
    const char* W3b = W3h + colf * 2;
    const char* W2b = W2h + colf * 2;

    float4 acc = f4z();

    // ---- U3: branchless fixed-2 groups; rare pair-start branch ----
    {
        float4 accp = f4z(), xp = f4z();
        int pp = 0;
#pragma unroll 4
        for (int e = 0; e < n3g; ++e) {
            uint4 E = __ldg(&g_ent3[e]);
            if (E.x & 0x80000000u) {                 // pair start (~8%)
                acc  = f4fma(xp, accp, acc);
                accp = f4z();
                unsigned P = __ldg(&g_pair3[pp++]);
                float4 xw = h4_to_f4(*reinterpret_cast<const uint2*>(Xb + (P & 0xffffu)));
                float4 xx = h4_to_f4(*reinterpret_cast<const uint2*>(Xb + (P >> 16)));
                xp = f4mul(xw, xx);
            }
            float4 xi = h4_to_f4(*reinterpret_cast<const uint2*>(Xb + (E.x & 0xffffu)));
            float4 wa = h4_to_f4(*reinterpret_cast<const uint2*>(W3b + (E.w & 0xffffu)));
            float4 wb = h4_to_f4(*reinterpret_cast<const uint2*>(W3b + (E.w >> 16)));
            float4 s  = f4muls(__uint_as_float(E.y), wa);
            s = f4fmas(__uint_as_float(E.z), wb, s);
            accp = f4fma(xi, s, accp);
        }
        acc = f4fma(xp, accp, acc);
    }

    // ---- U2: self-contained groups ----
    for (int e = 0; e < n2g; ++e) {
        uint4 E = __ldg(&g_ent2[e]);
        float4 xw = h4_to_f4(*reinterpret_cast<const uint2*>(Xb + (E.x & 0xffffu)));
        float4 xx = h4_to_f4(*reinterpret_cast<const uint2*>(Xb + (E.x >> 16)));
        float4 wa = h4_to_f4(*reinterpret_cast<const uint2*>(W2b + (E.w & 0xffffu)));
        float4 wb = h4_to_f4(*reinterpret_cast<const uint2*>(W2b + (E.w >> 16)));
        float4 s  = f4muls(__uint_as_float(E.y), wa);
        s = f4fmas(__uint_as_float(E.z), wb, s);
        acc = f4fma(f4mul(xw, xx), s, acc);
    }

    // ---- U1 ----
    {
        float4 d = f4z();
#pragma unroll
        for (int l = 0; l < LL; ++l) {
            float4 xv = h4_to_f4(*reinterpret_cast<const uint2*>(Xb + l * XROW));
            d = f4fmas(__ldg(U1 + l), xv, d);
        }
        acc = f4fma(W1r, d, acc);
    }

    if (valid)
        *reinterpret_cast<float4*>(out + (size_t)b * CC + c0) = acc;
}

// ---------------------------------------------------------------------------
extern "C" void kernel_launch(void* const* d_in, const int* in_sizes, int n_in,
                              void* d_out, int out_size)
{
    const float* x  = (const float*)d_in[0];   // [B,C,L]
    const float* y  = (const float*)d_in[1];   // [B,E]
    const float* U3 = (const float*)d_in[2];   // [16,16,16,23]
    const float* U2 = (const float*)d_in[3];   // [16,16,4]
    const float* U1 = (const float*)d_in[4];   // [16,1]
    const float* w3 = (const float*)d_in[5];   // [10,23,128]
    const float* w2 = (const float*)d_in[6];   // [10,4,128]
    const float* w1 = (const float*)d_in[7];   // [10,1,128]
    float* out = (float*)d_out;

    const int B = in_sizes[0] / (CC * LL);

    build_sparse_kernel<<<1, 1024>>>(U3, U2);

    cudaFuncSetAttribute(sym_contract_kernel,
                         cudaFuncAttributeMaxDynamicSharedMemorySize, SH_BYTES);
    const int grid = (B + NODES - 1) / NODES;
    sym_contract_kernel<<<grid, NODES * 32, SH_BYTES>>>(x, y, w3, w2, w1, U1, out, B);
}

// round 7
// speedup vs baseline: 2.5604x; 1.3015x over previous
#include <cuda_runtime.h>
#include <cuda_fp16.h>
#include <cstdint>

// ---------------------------------------------------------------------------
// SymmetricContraction. out[b,c] = W1*(u1.x) + sum_k W2_k x^T U2_k x
//                                + sum_k W3_k sum U3 x x x
// B=5888, C=128, L=16, E=10, P3=23, P2=4, P1=1
// Fixed-2-entry groups; X/W fp16 in smem; fp32 accumulate.
// S=2: two co-threads per (node, channel-quad) split the entry stream.
// ---------------------------------------------------------------------------

#define CC    128
#define LL    16
#define EE    10
#define PP3   23
#define PP2   4
#define NODES 8
#define THREADS (NODES*64)         // 512: warp pair per node (sub 0/1)
#define CPB   (NODES*CC)           // 1024 channels per block
#define XROW  (CPB*2)              // 2048 B : fp16 X row stride
#define W3R   (CPB*2)              // 2048 B : fp16 W row stride

#define NG3MAX (4096*12 + 8)
#define NG2MAX (512 + 8)

// device scratch (no allocation allowed)
__device__ uint4        g_ent3[NG3MAX];
__device__ uint4        g_ent2[NG2MAX];
__device__ unsigned int g_pair3[260];
__device__ unsigned int g_pairgrp[260];
__device__ unsigned int g_n3g, g_n2g, g_n2h;
__device__ unsigned int g_split_grp, g_split_pair;

// ---------------------------------------------------------------------------
__device__ __forceinline__ int block_exscan_1024(int cnt, int t, int* warp_sums, int* total)
{
    __syncthreads();
    const int lane = t & 31, wid = t >> 5;
    int inc = cnt;
#pragma unroll
    for (int d = 1; d < 32; d <<= 1) {
        int n = __shfl_up_sync(0xffffffffu, inc, d);
        if (lane >= d) inc += n;
    }
    if (lane == 31) warp_sums[wid] = inc;
    __syncthreads();
    if (wid == 0) {
        int v = warp_sums[lane];
#pragma unroll
        for (int d = 1; d < 32; d <<= 1) {
            int n = __shfl_up_sync(0xffffffffu, v, d);
            if (lane >= d) v += n;
        }
        warp_sums[lane] = v;
    }
    __syncthreads();
    *total = warp_sums[31];
    return inc - cnt + (wid ? warp_sums[wid - 1] : 0);
}

// ---------------------------------------------------------------------------
// U3 group (uint4): .x = i_byte_off(16b) | pairStart<<31
//                   .y = v1 (f32 bits)   .z = v2 (f32 bits, 0 if padded)
//                   .w = k1_byte_off(16b) | k2_byte_off<<16
// Pair record (uint): w_off(16b) | x_off<<16  (consumed in stream order)
// g_pairgrp[p] = group index where pair p starts (for stream splitting).
// ---------------------------------------------------------------------------
__global__ __launch_bounds__(1024)
void build_sparse_kernel(const float* __restrict__ U3, const float* __restrict__ U2)
{
    __shared__ int warp_sums[32];
    const int t = threadIdx.x;
    const int lane = t & 31;

    const int base = t * 92;
    int emit_cnt = 0;
#pragma unroll
    for (int g = 0; g < 4; ++g) {
        int c = 0;
        for (int k = 0; k < PP3; ++k) c += (U3[base + g * PP3 + k] != 0.f);
        emit_cnt += (c + 1) >> 1;
    }
    int total3;
    int gpos = block_exscan_1024(emit_cnt, t, warp_sums, &total3);
    const int gpos0 = gpos;

    unsigned ball  = __ballot_sync(0xffffffffu, emit_cnt > 0);
    unsigned below = ball & ((1u << lane) - 1u) & (0xFu << (lane & ~3));
    const bool first_nnz = (emit_cnt > 0) && (below == 0u);
    bool fp = first_nnz;

    for (int g = 0; g < 4; ++g) {
        const int gbase = base + g * PP3;
        const uint32_t i_off = (uint32_t)((t & 3) * 4 + g) * XROW;
        int k1 = 0; float v1 = 0.f; bool pending = false;
        for (int k = 0; k < PP3; ++k) {
            float v = U3[gbase + k];
            if (v != 0.f) {
                if (!pending) { k1 = k; v1 = v; pending = true; }
                else {
                    g_ent3[gpos++] = make_uint4(i_off | (fp ? 0x80000000u : 0u),
                                                __float_as_uint(v1), __float_as_uint(v),
                                                (uint32_t)k1 * W3R | ((uint32_t)k * W3R << 16));
                    fp = false; pending = false;
                }
            }
        }
        if (pending) {
            g_ent3[gpos++] = make_uint4(i_off | (fp ? 0x80000000u : 0u),
                                        __float_as_uint(v1), 0u,
                                        (uint32_t)k1 * W3R);
            fp = false;
        }
    }

    const bool quad_any = (((ball >> (lane & ~3)) & 0xFu) != 0u);
    const int lead_flag = (((t & 3) == 0) && quad_any) ? 1 : 0;
    int totalp;
    int pref = block_exscan_1024(lead_flag, t, warp_sums, &totalp);
    if (lead_flag) {
        uint32_t w  = (uint32_t)(t >> 6);
        uint32_t x2 = (uint32_t)(t >> 2) & 15u;
        g_pair3[pref] = (w * XROW) | ((x2 * XROW) << 16);
    }
    // pair ordinal for this quad (valid when quad_any)
    const int pair_ord = pref - (((t & 3) != 0 && quad_any) ? 1 : 0);
    if (first_nnz && pair_ord >= 0 && pair_ord < 260)
        g_pairgrp[pair_ord] = (unsigned)gpos0;

    // ---- U2 ----
    int emit2 = 0;
    if (t < 256) {
        int c = 0;
#pragma unroll
        for (int k = 0; k < PP2; ++k) c += (U2[t * PP2 + k] != 0.f);
        emit2 = (c + 1) >> 1;
    }
    int total2;
    int p2 = block_exscan_1024(emit2, t, warp_sums, &total2);
    if (t < 256) {
        const uint32_t wx = ((uint32_t)(t >> 4) * XROW) | (((uint32_t)(t & 15) * XROW) << 16);
        int k1 = 0; float v1 = 0.f; bool pending = false;
        for (int k = 0; k < PP2; ++k) {
            float v = U2[t * PP2 + k];
            if (v != 0.f) {
                if (!pending) { k1 = k; v1 = v; pending = true; }
                else {
                    g_ent2[p2++] = make_uint4(wx, __float_as_uint(v1), __float_as_uint(v),
                                              (uint32_t)k1 * W3R | ((uint32_t)k * W3R << 16));
                    pending = false;
                }
            }
        }
        if (pending)
            g_ent2[p2++] = make_uint4(wx, __float_as_uint(v1), 0u, (uint32_t)k1 * W3R);
    }

    __syncthreads();
    if (t == 0) {
        int pad3 = (total3 + 3) & ~3;
        for (int j = total3; j < pad3; ++j) g_ent3[j] = make_uint4(0, 0, 0, 0);
        g_n3g = (unsigned)pad3;
        g_n2g = (unsigned)total2;
        g_n2h = (unsigned)(total2 / 2);
        // split at pair boundary nearest to half the groups (defensive defaults)
        int half = total3 / 2, sp = 0;
        int np = (totalp < 260) ? totalp : 260;
        for (int p = 0; p < np; ++p)
            if ((int)g_pairgrp[p] <= half) sp = p;
        g_split_grp  = (totalp > 0) ? g_pairgrp[sp] : 0u;
        g_split_pair = (totalp > 0) ? (unsigned)sp : 0u;
    }
}

// ---------------------------------------------------------------------------
__device__ __forceinline__ float4 f4z() { return make_float4(0.f, 0.f, 0.f, 0.f); }
__device__ __forceinline__ float4 f4fma(float4 a, float4 b, float4 c) {
    return make_float4(fmaf(a.x, b.x, c.x), fmaf(a.y, b.y, c.y),
                       fmaf(a.z, b.z, c.z), fmaf(a.w, b.w, c.w));
}
__device__ __forceinline__ float4 f4fmas(float a, float4 b, float4 c) {
    return make_float4(fmaf(a, b.x, c.x), fmaf(a, b.y, c.y),
                       fmaf(a, b.z, c.z), fmaf(a, b.w, c.w));
}
__device__ __forceinline__ float4 f4muls(float a, float4 b) {
    return make_float4(a * b.x, a * b.y, a * b.z, a * b.w);
}
__device__ __forceinline__ float4 f4mul(float4 a, float4 b) {
    return make_float4(a.x * b.x, a.y * b.y, a.z * b.z, a.w * b.w);
}
__device__ __forceinline__ float4 f4add(float4 a, float4 b) {
    return make_float4(a.x + b.x, a.y + b.y, a.z + b.z, a.w + b.w);
}
__device__ __forceinline__ float4 h4_to_f4(uint2 u) {
    float2 a = __half22float2(*reinterpret_cast<__half2*>(&u.x));
    float2 b = __half22float2(*reinterpret_cast<__half2*>(&u.y));
    return make_float4(a.x, a.y, b.x, b.y);
}
__device__ __forceinline__ uint2 f4_to_h4(float4 a) {
    uint2 u;
    *reinterpret_cast<__half2*>(&u.x) = __float22half2_rn(make_float2(a.x, a.y));
    *reinterpret_cast<__half2*>(&u.y) = __float22half2_rn(make_float2(a.z, a.w));
    return u;
}

// smem: Xh fp16 [16][1024] | W3h fp16 [23][1024] | W2h fp16 [4][1024]
#define SM_X   0
#define SM_W3  (LL*CPB*2)                  // 32768
#define SM_W2  (SM_W3 + PP3*CPB*2)         // +47104
#define SH_BYTES (SM_W2 + PP2*CPB*2)       // 88064

__global__ __launch_bounds__(THREADS, 2)
void sym_contract_kernel(const float* __restrict__ x,
                         const float* __restrict__ y,
                         const float* __restrict__ w3,
                         const float* __restrict__ w2,
                         const float* __restrict__ w1,
                         const float* __restrict__ U1,
                         float* __restrict__ out,
                         int B)
{
    extern __shared__ char sm[];
    char* Xh  = sm + SM_X;
    char* W3h = sm + SM_W3;
    char* W2h = sm + SM_W2;

    const int tid  = threadIdx.x;
    const int lane = tid & 31;
    const int warp = tid >> 5;
    const int sub  = warp & 1;
    const int node = warp >> 1;
    const int b    = blockIdx.x * NODES + node;
    const bool valid = (b < B);
    const int c0   = lane * 4;
    const int colf = node * CC + c0;

    // ---- setup, split between subs ----
    float yr[EE];
#pragma unroll
    for (int e = 0; e < EE; ++e) yr[e] = valid ? __ldg(y + (size_t)b * EE + e) : 0.f;

    if (sub == 0) {
        // stage x (fp16 rows)
        if (valid) {
            const float4* xp = reinterpret_cast<const float4*>(x + ((size_t)b * CC + c0) * LL);
#pragma unroll
            for (int q = 0; q < 4; ++q) {
                float4 r0 = xp[0 * 4 + q], r1 = xp[1 * 4 + q];
                float4 r2 = xp[2 * 4 + q], r3 = xp[3 * 4 + q];
                *reinterpret_cast<uint2*>(Xh + (q * 4 + 0) * XROW + colf * 2) =
                    f4_to_h4(make_float4(r0.x, r1.x, r2.x, r3.x));
                *reinterpret_cast<uint2*>(Xh + (q * 4 + 1) * XROW + colf * 2) =
                    f4_to_h4(make_float4(r0.y, r1.y, r2.y, r3.y));
                *reinterpret_cast<uint2*>(Xh + (q * 4 + 2) * XROW + colf * 2) =
                    f4_to_h4(make_float4(r0.z, r1.z, r2.z, r3.z));
                *reinterpret_cast<uint2*>(Xh + (q * 4 + 3) * XROW + colf * 2) =
                    f4_to_h4(make_float4(r0.w, r1.w, r2.w, r3.w));
            }
        } else {
#pragma unroll
            for (int l = 0; l < LL; ++l)
                *reinterpret_cast<uint2*>(Xh + l * XROW + colf * 2) = make_uint2(0, 0);
        }
        // W3 rows [0, 11)
#pragma unroll
        for (int k = 0; k < 11; ++k) {
            float4 a = f4z();
#pragma unroll
            for (int e = 0; e < EE; ++e) {
                float4 wv = *reinterpret_cast<const float4*>(w3 + (size_t)(e * PP3 + k) * CC + c0);
                a = f4fmas(yr[e], wv, a);
            }
            *reinterpret_cast<uint2*>(W3h + k * W3R + colf * 2) = f4_to_h4(a);
        }
    } else {
        // W3 rows [11, 23)
#pragma unroll
        for (int k = 11; k < PP3; ++k) {
            float4 a = f4z();
#pragma unroll
            for (int e = 0; e < EE; ++e) {
                float4 wv = *reinterpret_cast<const float4*>(w3 + (size_t)(e * PP3 + k) * CC + c0);
                a = f4fmas(yr[e], wv, a);
            }
            *reinterpret_cast<uint2*>(W3h + k * W3R + colf * 2) = f4_to_h4(a);
        }
        // W2 all
#pragma unroll
        for (int k = 0; k < PP2; ++k) {
            float4 a = f4z();
#pragma unroll
            for (int e = 0; e < EE; ++e) {
                float4 wv = *reinterpret_cast<const float4*>(w2 + (size_t)(e * PP2 + k) * CC + c0);
                a = f4fmas(yr[e], wv, a);
            }
            *reinterpret_cast<uint2*>(W2h + k * W3R + colf * 2) = f4_to_h4(a);
        }
    }
    float4 W1r = f4z();
    if (sub == 1) {
#pragma unroll
        for (int e = 0; e < EE; ++e) {
            float4 wv = *reinterpret_cast<const float4*>(w1 + (size_t)e * CC + c0);
            W1r = f4fmas(yr[e], wv, W1r);
        }
    }
    __syncthreads();

    const int n3g = (int)g_n3g;
    const int n2g = (int)g_n2g;
    const int n2h = (int)g_n2h;
    const int sgrp  = (int)g_split_grp;
    const int spair = (int)g_split_pair;

    const int e0 = sub ? sgrp : 0;
    const int e1 = sub ? n3g  : sgrp;
    int       pp = sub ? spair : 0;
    const int u0 = sub ? n2h : 0;
    const int u1 = sub ? n2g : n2h;

    const char* Xb  = Xh  + colf * 2;
    const char* W3b = W3h + colf * 2;
    const char* W2b = W2h + colf * 2;

    float4 acc = f4z();

    // ---- U3 half-stream: branchless fixed-2 groups ----
    {
        float4 accp = f4z(), xp = f4z();
#pragma unroll 4
        for (int e = e0; e < e1; ++e) {
            uint4 E = __ldg(&g_ent3[e]);
            if (E.x & 0x80000000u) {                 // pair start (~8%)
                acc  = f4fma(xp, accp, acc);
                accp = f4z();
                unsigned P = __ldg(&g_pair3[pp++]);
                float4 xw = h4_to_f4(*reinterpret_cast<const uint2*>(Xb + (P & 0xffffu)));
                float4 xx = h4_to_f4(*reinterpret_cast<const uint2*>(Xb + (P >> 16)));
                xp = f4mul(xw, xx);
            }
            float4 xi = h4_to_f4(*reinterpret_cast<const uint2*>(Xb + (E.x & 0xffffu)));
            float4 wa = h4_to_f4(*reinterpret_cast<const uint2*>(W3b + (E.w & 0xffffu)));
            float4 wb = h4_to_f4(*reinterpret_cast<const uint2*>(W3b + (E.w >> 16)));
            float4 s  = f4muls(__uint_as_float(E.y), wa);
            s = f4fmas(__uint_as_float(E.z), wb, s);
            accp = f4fma(xi, s, accp);
        }
        acc = f4fma(xp, accp, acc);
    }

    // ---- U2 half-stream ----
    for (int e = u0; e < u1; ++e) {
        uint4 E = __ldg(&g_ent2[e]);
        float4 xw = h4_to_f4(*reinterpret_cast<const uint2*>(Xb + (E.x & 0xffffu)));
        float4 xx = h4_to_f4(*reinterpret_cast<const uint2*>(Xb + (E.x >> 16)));
        float4 wa = h4_to_f4(*reinterpret_cast<const uint2*>(W2b + (E.w & 0xffffu)));
        float4 wb = h4_to_f4(*reinterpret_cast<const uint2*>(W2b + (E.w >> 16)));
        float4 s  = f4muls(__uint_as_float(E.y), wa);
        s = f4fmas(__uint_as_float(E.z), wb, s);
        acc = f4fma(f4mul(xw, xx), s, acc);
    }

    // ---- U1 (sub 1 only) ----
    if (sub == 1) {
        float4 d = f4z();
#pragma unroll
        for (int l = 0; l < LL; ++l) {
            float4 xv = h4_to_f4(*reinterpret_cast<const uint2*>(Xb + l * XROW));
            d = f4fmas(__ldg(U1 + l), xv, d);
        }
        acc = f4fma(W1r, d, acc);
    }

    // ---- combine subs (scratch reuses X region) ----
    __syncthreads();
    if (sub == 1)
        *reinterpret_cast<float4*>(sm + colf * 16) = acc;
    __syncthreads();
    if (sub == 0 && valid) {
        float4 o = *reinterpret_cast<float4*>(sm + colf * 16);
        *reinterpret_cast<float4*>(out + (size_t)b * CC + c0) = f4add(acc, o);
    }
}

// ---------------------------------------------------------------------------
extern "C" void kernel_launch(void* const* d_in, const int* in_sizes, int n_in,
                              void* d_out, int out_size)
{
    const float* x  = (const float*)d_in[0];   // [B,C,L]
    const float* y  = (const float*)d_in[1];   // [B,E]
    const float* U3 = (const float*)d_in[2];   // [16,16,16,23]
    const float* U2 = (const float*)d_in[3];   // [16,16,4]
    const float* U1 = (const float*)d_in[4];   // [16,1]
    const float* w3 = (const float*)d_in[5];   // [10,23,128]
    const float* w2 = (const float*)d_in[6];   // [10,4,128]
    const float* w1 = (const float*)d_in[7];   // [10,1,128]
    float* out = (float*)d_out;

    const int B = in_sizes[0] / (CC * LL);

    build_sparse_kernel<<<1, 1024>>>(U3, U2);

    cudaFuncSetAttribute(sym_contract_kernel,
                         cudaFuncAttributeMaxDynamicSharedMemorySize, SH_BYTES);
    const int grid = (B + NODES - 1) / NODES;
    sym_contract_kernel<<<grid, THREADS, SH_BYTES>>>(x, y, w3, w2, w1, U1, out, B);
}

// round 9
// speedup vs baseline: 2.6804x; 1.0469x over previous
#include <cuda_runtime.h>
#include <cuda_fp16.h>
#include <cstdint>

// ---------------------------------------------------------------------------
// SymmetricContraction. out[b,c] = W1*(u1.x) + sum_k W2_k x^T U2_k x
//                                + sum_k W3_k sum U3 x x x
// B=5888, C=128, L=16, E=10, P3=23, P2=4, P1=1
// Fixed-2-entry groups; X/W fp16 in smem; s-chain in half2; fp32 accumulate.
// S=2: two co-threads per (node, channel-quad) split the entry stream.
// ---------------------------------------------------------------------------

#define CC    128
#define LL    16
#define EE    10
#define PP3   23
#define PP2   4
#define NODES 8
#define THREADS (NODES*64)         // 512: warp pair per node (sub 0/1)
#define CPB   (NODES*CC)           // 1024 channels per block
#define XROW  (CPB*2)              // 2048 B : fp16 X row stride
#define W3R   (CPB*2)              // 2048 B : fp16 W row stride

#define NG3MAX (4096*12 + 8)
#define NG2MAX (512 + 8)

// device scratch (no allocation allowed)
__device__ uint4        g_ent3[NG3MAX];
__device__ uint4        g_ent2[NG2MAX];
__device__ unsigned int g_pair3[260];
__device__ unsigned int g_pairgrp[260];
__device__ unsigned int g_n3g, g_n2g, g_n2h;
__device__ unsigned int g_split_grp, g_split_pair;

// ---------------------------------------------------------------------------
__device__ __forceinline__ int block_exscan_1024(int cnt, int t, int* warp_sums, int* total)
{
    __syncthreads();
    const int lane = t & 31, wid = t >> 5;
    int inc = cnt;
#pragma unroll
    for (int d = 1; d < 32; d <<= 1) {
        int n = __shfl_up_sync(0xffffffffu, inc, d);
        if (lane >= d) inc += n;
    }
    if (lane == 31) warp_sums[wid] = inc;
    __syncthreads();
    if (wid == 0) {
        int v = warp_sums[lane];
#pragma unroll
        for (int d = 1; d < 32; d <<= 1) {
            int n = __shfl_up_sync(0xffffffffu, v, d);
            if (lane >= d) v += n;
        }
        warp_sums[lane] = v;
    }
    __syncthreads();
    *total = warp_sums[31];
    return inc - cnt + (wid ? warp_sums[wid - 1] : 0);
}

__device__ __forceinline__ uint32_t pack_h2(float v)
{
    __half2 t = __float2half2_rn(v);
    return *reinterpret_cast<uint32_t*>(&t);
}

// ---------------------------------------------------------------------------
// U3 group (uint4): .x = i_byte_off(16b) | pairStart<<31
//                   .y = half2(v1,v1)    .z = half2(v2,v2) (0 if padded)
//                   .w = k1_byte_off(16b) | k2_byte_off<<16
// Pair record (uint): w_off(16b) | x_off<<16  (consumed in stream order)
// g_pairgrp[p] = group index where pair p starts (for stream splitting).
// ---------------------------------------------------------------------------
__global__ __launch_bounds__(1024)
void build_sparse_kernel(const float* __restrict__ U3, const float* __restrict__ U2)
{
    __shared__ int warp_sums[32];
    const int t = threadIdx.x;
    const int lane = t & 31;

    const int base = t * 92;
    int emit_cnt = 0;
#pragma unroll
    for (int g = 0; g < 4; ++g) {
        int c = 0;
        for (int k = 0; k < PP3; ++k) c += (U3[base + g * PP3 + k] != 0.f);
        emit_cnt += (c + 1) >> 1;
    }
    int total3;
    int gpos = block_exscan_1024(emit_cnt, t, warp_sums, &total3);
    const int gpos0 = gpos;

    unsigned ball  = __ballot_sync(0xffffffffu, emit_cnt > 0);
    unsigned below = ball & ((1u << lane) - 1u) & (0xFu << (lane & ~3));
    const bool first_nnz = (emit_cnt > 0) && (below == 0u);
    bool fp = first_nnz;

    for (int g = 0; g < 4; ++g) {
        const int gbase = base + g * PP3;
        const uint32_t i_off = (uint32_t)((t & 3) * 4 + g) * XROW;
        int k1 = 0; float v1 = 0.f; bool pending = false;
        for (int k = 0; k < PP3; ++k) {
            float v = U3[gbase + k];
            if (v != 0.f) {
                if (!pending) { k1 = k; v1 = v; pending = true; }
                else {
                    g_ent3[gpos++] = make_uint4(i_off | (fp ? 0x80000000u : 0u),
                                                pack_h2(v1), pack_h2(v),
                                                (uint32_t)k1 * W3R | ((uint32_t)k * W3R << 16));
                    fp = false; pending = false;
                }
            }
        }
        if (pending) {
            g_ent3[gpos++] = make_uint4(i_off | (fp ? 0x80000000u : 0u),
                                        pack_h2(v1), 0u,
                                        (uint32_t)k1 * W3R);
            fp = false;
        }
    }

    const bool quad_any = (((ball >> (lane & ~3)) & 0xFu) != 0u);
    const int lead_flag = (((t & 3) == 0) && quad_any) ? 1 : 0;
    int totalp;
    int pref = block_exscan_1024(lead_flag, t, warp_sums, &totalp);
    if (lead_flag) {
        uint32_t w  = (uint32_t)(t >> 6);
        uint32_t x2 = (uint32_t)(t >> 2) & 15u;
        g_pair3[pref] = (w * XROW) | ((x2 * XROW) << 16);
    }
    // pair ordinal for this quad (valid when quad_any)
    const int pair_ord = pref - (((t & 3) != 0 && quad_any) ? 1 : 0);
    if (first_nnz && pair_ord >= 0 && pair_ord < 260)
        g_pairgrp[pair_ord] = (unsigned)gpos0;

    // ---- U2 ----
    int emit2 = 0;
    if (t < 256) {
        int c = 0;
#pragma unroll
        for (int k = 0; k < PP2; ++k) c += (U2[t * PP2 + k] != 0.f);
        emit2 = (c + 1) >> 1;
    }
    int total2;
    int p2 = block_exscan_1024(emit2, t, warp_sums, &total2);
    if (t < 256) {
        const uint32_t wx = ((uint32_t)(t >> 4) * XROW) | (((uint32_t)(t & 15) * XROW) << 16);
        int k1 = 0; float v1 = 0.f; bool pending = false;
        for (int k = 0; k < PP2; ++k) {
            float v = U2[t * PP2 + k];
            if (v != 0.f) {
                if (!pending) { k1 = k; v1 = v; pending = true; }
                else {
                    g_ent2[p2++] = make_uint4(wx, pack_h2(v1), pack_h2(v),
                                              (uint32_t)k1 * W3R | ((uint32_t)k * W3R << 16));
                    pending = false;
                }
            }
        }
        if (pending)
            g_ent2[p2++] = make_uint4(wx, pack_h2(v1), 0u, (uint32_t)k1 * W3R);
    }

    __syncthreads();
    if (t == 0) {
        int pad3 = (total3 + 3) & ~3;
        for (int j = total3; j < pad3; ++j) g_ent3[j] = make_uint4(0, 0, 0, 0);
        g_n3g = (unsigned)pad3;
        g_n2g = (unsigned)total2;
        g_n2h = (unsigned)(total2 / 2);
        // split at pair boundary nearest to half the groups (defensive defaults)
        int half = total3 / 2, sp = 0;
        int np = (totalp < 260) ? totalp : 260;
        for (int p = 0; p < np; ++p)
            if ((int)g_pairgrp[p] <= half) sp = p;
        g_split_grp  = (totalp > 0) ? g_pairgrp[sp] : 0u;
        g_split_pair = (totalp > 0) ? (unsigned)sp : 0u;
    }
}

// ---------------------------------------------------------------------------
__device__ __forceinline__ float4 f4z() { return make_float4(0.f, 0.f, 0.f, 0.f); }
__device__ __forceinline__ float4 f4fma(float4 a, float4 b, float4 c) {
    return make_float4(fmaf(a.x, b.x, c.x), fmaf(a.y, b.y, c.y),
                       fmaf(a.z, b.z, c.z), fmaf(a.w, b.w, c.w));
}
__device__ __forceinline__ float4 f4fmas(float a, float4 b, float4 c) {
    return make_float4(fmaf(a, b.x, c.x), fmaf(a, b.y, c.y),
                       fmaf(a, b.z, c.z), fmaf(a, b.w, c.w));
}
__device__ __forceinline__ float4 f4mul(float4 a, float4 b) {
    return make_float4(a.x * b.x, a.y * b.y, a.z * b.z, a.w * b.w);
}
__device__ __forceinline__ float4 f4add(float4 a, float4 b) {
    return make_float4(a.x + b.x, a.y + b.y, a.z + b.z, a.w + b.w);
}
__device__ __forceinline__ float4 h4_to_f4(uint2 u) {
    float2 a = __half22float2(*reinterpret_cast<__half2*>(&u.x));
    float2 b = __half22float2(*reinterpret_cast<__half2*>(&u.y));
    return make_float4(a.x, a.y, b.x, b.y);
}
__device__ __forceinline__ uint2 f4_to_h4(float4 a) {
    uint2 u;
    *reinterpret_cast<__half2*>(&u.x) = __float22half2_rn(make_float2(a.x, a.y));
    *reinterpret_cast<__half2*>(&u.y) = __float22half2_rn(make_float2(a.z, a.w));
    return u;
}
// s = v1*wa + v2*wb in half2, returned as fp32 quad
__device__ __forceinline__ float4 schain(uint32_t v1u, uint32_t v2u, uint2 wau, uint2 wbu)
{
    __half2 v1 = *reinterpret_cast<__half2*>(&v1u);
    __half2 v2 = *reinterpret_cast<__half2*>(&v2u);
    __half2 s0 = __hfma2(v2, *reinterpret_cast<__half2*>(&wbu.x),
                         __hmul2(v1, *reinterpret_cast<__half2*>(&wau.x)));
    __half2 s1 = __hfma2(v2, *reinterpret_cast<__half2*>(&wbu.y),
                         __hmul2(v1, *reinterpret_cast<__half2*>(&wau.y)));
    float2 a = __half22float2(s0);
    float2 b = __half22float2(s1);
    return make_float4(a.x, a.y, b.x, b.y);
}

// smem: Xh fp16 [16][1024] | W3h fp16 [23][1024] | W2h fp16 [4][1024]
#define SM_X   0
#define SM_W3  (LL*CPB*2)                  // 32768
#define SM_W2  (SM_W3 + PP3*CPB*2)         // +47104
#define SH_BYTES (SM_W2 + PP2*CPB*2)       // 88064

__global__ __launch_bounds__(THREADS, 2)
void sym_contract_kernel(const float* __restrict__ x,
                         const float* __restrict__ y,
                         const float* __restrict__ w3,
                         const float* __restrict__ w2,
                         const float* __restrict__ w1,
                         const float* __restrict__ U1,
                         float* __restrict__ out,
                         int B)
{
    extern __shared__ char sm[];
    char* Xh  = sm + SM_X;
    char* W3h = sm + SM_W3;
    char* W2h = sm + SM_W2;

    const int tid  = threadIdx.x;
    const int lane = tid & 31;
    const int warp = tid >> 5;
    const int sub  = warp & 1;
    const int node = warp >> 1;
    const int b    = blockIdx.x * NODES + node;
    const bool valid = (b < B);
    const int c0   = lane * 4;
    const int colf = node * CC + c0;

    // ---- setup, split between subs ----
    float yr[EE];
#pragma unroll
    for (int e = 0; e < EE; ++e) yr[e] = valid ? __ldg(y + (size_t)b * EE + e) : 0.f;

    if (sub == 0) {
        // stage x (fp16 rows)
        if (valid) {
            const float4* xp = reinterpret_cast<const float4*>(x + ((size_t)b * CC + c0) * LL);
#pragma unroll
            for (int q = 0; q < 4; ++q) {
                float4 r0 = xp[0 * 4 + q], r1 = xp[1 * 4 + q];
                float4 r2 = xp[2 * 4 + q], r3 = xp[3 * 4 + q];
                *reinterpret_cast<uint2*>(Xh + (q * 4 + 0) * XROW + colf * 2) =
                    f4_to_h4(make_float4(r0.x, r1.x, r2.x, r3.x));
                *reinterpret_cast<uint2*>(Xh + (q * 4 + 1) * XROW + colf * 2) =
                    f4_to_h4(make_float4(r0.y, r1.y, r2.y, r3.y));
                *reinterpret_cast<uint2*>(Xh + (q * 4 + 2) * XROW + colf * 2) =
                    f4_to_h4(make_float4(r0.z, r1.z, r2.z, r3.z));
                *reinterpret_cast<uint2*>(Xh + (q * 4 + 3) * XROW + colf * 2) =
                    f4_to_h4(make_float4(r0.w, r1.w, r2.w, r3.w));
            }
        } else {
#pragma unroll
            for (int l = 0; l < LL; ++l)
                *reinterpret_cast<uint2*>(Xh + l * XROW + colf * 2) = make_uint2(0, 0);
        }
        // W3 rows [0, 11)
#pragma unroll
        for (int k = 0; k < 11; ++k) {
            float4 a = f4z();
#pragma unroll
            for (int e = 0; e < EE; ++e) {
                float4 wv = *reinterpret_cast<const float4*>(w3 + (size_t)(e * PP3 + k) * CC + c0);
                a = f4fmas(yr[e], wv, a);
            }
            *reinterpret_cast<uint2*>(W3h + k * W3R + colf * 2) = f4_to_h4(a);
        }
    } else {
        // W3 rows [11, 23)
#pragma unroll
        for (int k = 11; k < PP3; ++k) {
            float4 a = f4z();
#pragma unroll
            for (int e = 0; e < EE; ++e) {
                float4 wv = *reinterpret_cast<const float4*>(w3 + (size_t)(e * PP3 + k) * CC + c0);
                a = f4fmas(yr[e], wv, a);
            }
            *reinterpret_cast<uint2*>(W3h + k * W3R + colf * 2) = f4_to_h4(a);
        }
        // W2 all
#pragma unroll
        for (int k = 0; k < PP2; ++k) {
            float4 a = f4z();
#pragma unroll
            for (int e = 0; e < EE; ++e) {
                float4 wv = *reinterpret_cast<const float4*>(w2 + (size_t)(e * PP2 + k) * CC + c0);
                a = f4fmas(yr[e], wv, a);
            }
            *reinterpret_cast<uint2*>(W2h + k * W3R + colf * 2) = f4_to_h4(a);
        }
    }
    float4 W1r = f4z();
    if (sub == 1) {
#pragma unroll
        for (int e = 0; e < EE; ++e) {
            float4 wv = *reinterpret_cast<const float4*>(w1 + (size_t)e * CC + c0);
            W1r = f4fmas(yr[e], wv, W1r);
        }
    }
    __syncthreads();

    const int n3g = (int)g_n3g;
    const int n2g = (int)g_n2g;
    const int n2h = (int)g_n2h;
    const int sgrp  = (int)g_split_grp;
    const int spair = (int)g_split_pair;

    const int e0 = sub ? sgrp : 0;
    const int e1 = sub ? n3g  : sgrp;
    int       pp = sub ? spair : 0;
    const int u0 = sub ? n2h : 0;
    const int u1 = sub ? n2g : n2h;

    const char* Xb  = Xh  + colf * 2;
    const char* W3b = W3h + colf * 2;
    const char* W2b = W2h + colf * 2;

    float4 acc = f4z();

    // ---- U3 half-stream: branchless fixed-2 groups, half2 s-chain ----
    {
        float4 accp = f4z(), xp = f4z();
#pragma unroll 4
        for (int e = e0; e < e1; ++e) {
            uint4 E = __ldg(&g_ent3[e]);
            if (E.x & 0x80000000u) {                 // pair start (~8%)
                acc  = f4fma(xp, accp, acc);
                accp = f4z();
                unsigned P = __ldg(&g_pair3[pp++]);
                float4 xw = h4_to_f4(*reinterpret_cast<const uint2*>(Xb + (P & 0xffffu)));
                float4 xx = h4_to_f4(*reinterpret_cast<const uint2*>(Xb + (P >> 16)));
                xp = f4mul(xw, xx);
            }
            uint2 wau = *reinterpret_cast<const uint2*>(W3b + (E.w & 0xffffu));
            uint2 wbu = *reinterpret_cast<const uint2*>(W3b + (E.w >> 16));
            float4 s  = schain(E.y, E.z, wau, wbu);
            float4 xi = h4_to_f4(*reinterpret_cast<const uint2*>(Xb + (E.x & 0xffffu)));
            accp = f4fma(xi, s, accp);
        }
        acc = f4fma(xp, accp, acc);
    }

    // ---- U2 half-stream ----
    for (int e = u0; e < u1; ++e) {
        uint4 E = __ldg(&g_ent2[e]);
        float4 xw = h4_to_f4(*reinterpret_cast<const uint2*>(Xb + (E.x & 0xffffu)));
        float4 xx = h4_to_f4(*reinterpret_cast<const uint2*>(Xb + (E.x >> 16)));
        uint2 wau = *reinterpret_cast<const uint2*>(W2b + (E.w & 0xffffu));
        uint2 wbu = *reinterpret_cast<const uint2*>(W2b + (E.w >> 16));
        float4 s  = schain(E.y, E.z, wau, wbu);
        acc = f4fma(f4mul(xw, xx), s, acc);
    }

    // ---- U1 (sub 1 only) ----
    if (sub == 1) {
        float4 d = f4z();
#pragma unroll
        for (int l = 0; l < LL; ++l) {
            float4 xv = h4_to_f4(*reinterpret_cast<const uint2*>(Xb + l * XROW));
            d = f4fmas(__ldg(U1 + l), xv, d);
        }
        acc = f4fma(W1r, d, acc);
    }

    // ---- combine subs (scratch reuses X region) ----
    __syncthreads();
    if (sub == 1)
        *reinterpret_cast<float4*>(sm + colf * 16) = acc;
    __syncthreads();
    if (sub == 0 && valid) {
        float4 o = *reinterpret_cast<float4*>(sm + colf * 16);
        *reinterpret_cast<float4*>(out + (size_t)b * CC + c0) = f4add(acc, o);
    }
}

// ---------------------------------------------------------------------------
extern "C" void kernel_launch(void* const* d_in, const int* in_sizes, int n_in,
                              void* d_out, int out_size)
{
    const float* x  = (const float*)d_in[0];   // [B,C,L]
    const float* y  = (const float*)d_in[1];   // [B,E]
    const float* U3 = (const float*)d_in[2];   // [16,16,16,23]
    const float* U2 = (const float*)d_in[3];   // [16,16,4]
    const float* U1 = (const float*)d_in[4];   // [16,1]
    const float* w3 = (const float*)d_in[5];   // [10,23,128]
    const float* w2 = (const float*)d_in[6];   // [10,4,128]
    const float* w1 = (const float*)d_in[7];   // [10,1,128]
    float* out = (float*)d_out;

    const int B = in_sizes[0] / (CC * LL);

    build_sparse_kernel<<<1, 1024>>>(U3, U2);

    cudaFuncSetAttribute(sym_contract_kernel,
                         cudaFuncAttributeMaxDynamicSharedMemorySize, SH_BYTES);
    const int grid = (B + NODES - 1) / NODES;
    sym_contract_kernel<<<grid, THREADS, SH_BYTES>>>(x, y, w3, w2, w1, U1, out, B);
}

// round 10
// speedup vs baseline: 4.2020x; 1.5677x over previous
#include <cuda_runtime.h>
#include <cuda_fp16.h>
#include <cstdint>

// ---------------------------------------------------------------------------
// SymmetricContraction via monomial GEMM.
// out[b,c] = sum_k3 W3[k]*Q3[k] + U2/U1 scalar terms
//   Q3[b,c,k] = sum_T A[T,k] * m[b,c,T],  m = x_a x_b x_c over sorted triples
// GEMM per node (M=128 channels) with mma.sync.m16n8k16 f16 in / f32 accum.
// B=5888, C=128, L=16, E=10, P3=23, P2=4, P1=1
// ---------------------------------------------------------------------------

#define CC   128
#define LL   16
#define EE   10
#define PP3  23
#define PP2  4
#define MAXK 832        // sorted triples <= 816, padded to mult of 16
#define NPAD 24         // GEMM N: 23 paths + 1 zero col

// ---- device globals (no allocation allowed) ----
__device__ float    g_Af[MAXK][NPAD];     // fp32 A accumulation
__device__ __half   g_AhT[NPAD][MAXK];    // A transposed, fp16 (B operand src)
__device__ uint32_t g_spec[MAXK];         // a | b<<8 | c<<16
__device__ uint2    g_e2[1040];           // U2: (w|x<<8|k<<16, f32 v)
__device__ unsigned g_K;                  // padded K
__device__ unsigned g_n2;

// ---------------------------------------------------------------------------
__device__ __forceinline__ int block_exscan_1024(int cnt, int t, int* warp_sums, int* total)
{
    __syncthreads();
    const int lane = t & 31, wid = t >> 5;
    int inc = cnt;
#pragma unroll
    for (int d = 1; d < 32; d <<= 1) {
        int n = __shfl_up_sync(0xffffffffu, inc, d);
        if (lane >= d) inc += n;
    }
    if (lane == 31) warp_sums[wid] = inc;
    __syncthreads();
    if (wid == 0) {
        int v = warp_sums[lane];
#pragma unroll
        for (int d = 1; d < 32; d <<= 1) {
            int n = __shfl_up_sync(0xffffffffu, v, d);
            if (lane >= d) v += n;
        }
        warp_sums[lane] = v;
    }
    __syncthreads();
    *total = warp_sums[31];
    return inc - cnt + (wid ? warp_sums[wid - 1] : 0);
}

__device__ __forceinline__ void sort3(int& a, int& b, int& c)
{
    int t;
    if (a > b) { t = a; a = b; b = t; }
    if (b > c) { t = b; b = c; c = t; }
    if (a > b) { t = a; a = b; b = t; }
}

// ---------------------------------------------------------------------------
// Build: dedup sorted triples, accumulate A (atomicAdd), emit spec + U2 list.
// One block, 1024 threads. Thread t owns U3 elems [t*92, t*92+92) as before:
// w = t>>6, x2 = (t>>2)&15, i = (t&3)*4+g.
// ---------------------------------------------------------------------------
__global__ __launch_bounds__(1024)
void build_tables_kernel(const float* __restrict__ U3, const float* __restrict__ U2)
{
    __shared__ int            warp_sums[32];
    __shared__ unsigned char  used3[4096];
    __shared__ unsigned short cellid[4096];
    const int t = threadIdx.x;

    // zero A accumulator + spec
    for (int idx = t; idx < MAXK * NPAD; idx += 1024)
        (&g_Af[0][0])[idx] = 0.f;
    for (int idx = t; idx < MAXK; idx += 1024)
        g_spec[idx] = 0u;
#pragma unroll
    for (int j = 0; j < 4; ++j) used3[t * 4 + j] = 0;
    __syncthreads();

    // mark used sorted triples
    const int base = t * 92;
    const int w  = t >> 6;
    const int x2 = (t >> 2) & 15;
#pragma unroll
    for (int g = 0; g < 4; ++g) {
        const int i = (t & 3) * 4 + g;
        for (int k = 0; k < PP3; ++k) {
            if (U3[base + g * PP3 + k] != 0.f) {
                int a = w, b = x2, c = i;
                sort3(a, b, c);
                used3[a * 256 + b * 16 + c] = 1;
            }
        }
    }
    __syncthreads();

    // compact cell ids (order preserved -> deterministic)
    int cnt = 0;
#pragma unroll
    for (int j = 0; j < 4; ++j) cnt += used3[t * 4 + j];
    int K3;
    int pos = block_exscan_1024(cnt, t, warp_sums, &K3);
#pragma unroll
    for (int j = 0; j < 4; ++j) {
        const int cell = t * 4 + j;
        if (used3[cell]) {
            cellid[cell] = (unsigned short)pos;
            const int a = cell >> 8, b = (cell >> 4) & 15, c = cell & 15;
            g_spec[pos] = (uint32_t)a | ((uint32_t)b << 8) | ((uint32_t)c << 16);
            ++pos;
        }
    }
    if (t == 0) g_K = (unsigned)((K3 + 15) & ~15);
    __syncthreads();

    // accumulate A
#pragma unroll
    for (int g = 0; g < 4; ++g) {
        const int i = (t & 3) * 4 + g;
        for (int k = 0; k < PP3; ++k) {
            float v = U3[base + g * PP3 + k];
            if (v != 0.f) {
                int a = w, b = x2, c = i;
                sort3(a, b, c);
                atomicAdd(&g_Af[cellid[a * 256 + b * 16 + c]][k], v);
            }
        }
    }

    // U2 list (per-nnz)
    int cnt2 = 0;
    if (t < 256) {
#pragma unroll
        for (int k = 0; k < PP2; ++k) cnt2 += (U2[t * PP2 + k] != 0.f);
    }
    int total2;
    int p2 = block_exscan_1024(cnt2, t, warp_sums, &total2);
    if (t < 256) {
        const uint32_t wx = (uint32_t)(t >> 4) | ((uint32_t)(t & 15) << 8);
        for (int k = 0; k < PP2; ++k) {
            float v = U2[t * PP2 + k];
            if (v != 0.f) {
                g_e2[p2] = make_uint2(wx | ((uint32_t)k << 16), __float_as_uint(v));
                ++p2;
            }
        }
    }
    if (t == 0) g_n2 = (unsigned)total2;

    __threadfence();
    __syncthreads();

    // convert transposed fp16 (covers all MAXK rows; pads are zero)
    for (int idx = t; idx < NPAD * MAXK; idx += 1024) {
        const int n = idx / MAXK, m = idx % MAXK;
        g_AhT[n][m] = __float2half(g_Af[m][n]);
    }
}

// ---------------------------------------------------------------------------
// helpers
// ---------------------------------------------------------------------------
__device__ __forceinline__ float4 f4mul(float4 a, float4 b) {
    return make_float4(a.x * b.x, a.y * b.y, a.z * b.z, a.w * b.w);
}
__device__ __forceinline__ uint2 f4_to_h4(float4 a) {
    uint2 u;
    *reinterpret_cast<__half2*>(&u.x) = __float22half2_rn(make_float2(a.x, a.y));
    *reinterpret_cast<__half2*>(&u.y) = __float22half2_rn(make_float2(a.z, a.w));
    return u;
}
__device__ __forceinline__ uint32_t pk16(unsigned short lo, unsigned short hi) {
    return (uint32_t)lo | ((uint32_t)hi << 16);
}

#define MMA16816(d0,d1,d2,d3,a0,a1,a2,a3,b0,b1)                         \
    asm volatile("mma.sync.aligned.m16n8k16.row.col.f32.f16.f16.f32 "   \
        "{%0,%1,%2,%3}, {%4,%5,%6,%7}, {%8,%9}, {%0,%1,%2,%3};"         \
        : "+f"(d0), "+f"(d1), "+f"(d2), "+f"(d3)                        \
        : "r"(a0), "r"(a1), "r"(a2), "r"(a3), "r"(b0), "r"(b1))

// ---------------------------------------------------------------------------
// smem layout (bytes), block = 2 nodes x 128 threads
// ---------------------------------------------------------------------------
#define AHT_ROW   1680                       // MAXK*2 (=1664) + 16 pad
#define OFF_AHT   0
#define OFF_SPEC  (NPAD * AHT_ROW)           // 40320
#define OFF_NODE  (OFF_SPEC + MAXK * 4)      // 43648
#define XS_ROW    512                        // 128 fp32
#define MS_ROW    264                        // 128 fp16 + 8 pad
#define MS_BUF    (16 * MS_ROW)              // 4224
#define W3_ROW    520                        // 128 fp32 + 8 pad
#define NB_XS     0
#define NB_MS     (NB_XS + LL * XS_ROW)      // 8192
#define NB_W3     (NB_MS + 2 * MS_BUF)       // 16640
#define NB_W2     (NB_W3 + NPAD * W3_ROW)    // 29120
#define NB_W1     (NB_W2 + PP2 * 256)        // 30144
#define NB_OUT    (NB_W1 + 512)              // 30656
#define NODE_BYTES (NB_OUT + 512)            // 31168
#define SH_BYTES  (OFF_NODE + 2 * NODE_BYTES) // 105984

__global__ __launch_bounds__(256, 2)
void sym_gemm_kernel(const float* __restrict__ x,
                     const float* __restrict__ y,
                     const float* __restrict__ w3,
                     const float* __restrict__ w2,
                     const float* __restrict__ w1,
                     const float* __restrict__ U1,
                     float* __restrict__ out,
                     int B)
{
    extern __shared__ char sm[];
    const int tid  = threadIdx.x;
    const int node = tid >> 7;
    const int wt   = tid & 127;               // channel for setup phases
    const int b    = blockIdx.x * 2 + node;
    const bool valid = (b < B);

    char* nb  = sm + OFF_NODE + node * NODE_BYTES;
    char* xsm = nb + NB_XS;
    char* msm = nb + NB_MS;
    char* w3f = nb + NB_W3;
    char* w2h = nb + NB_W2;
    float* w1f = reinterpret_cast<float*>(nb + NB_W1);
    float* outs = reinterpret_cast<float*>(nb + NB_OUT);

    const int KP  = (int)g_K;
    const int n2  = (int)g_n2;

    // ---- copy AhT + spec into smem ----
    for (int idx = tid; idx < NPAD * 104; idx += 256) {
        const int r = idx / 104, j = idx % 104;
        *reinterpret_cast<uint4*>(sm + OFF_AHT + r * AHT_ROW + j * 16) =
            *reinterpret_cast<const uint4*>(reinterpret_cast<const char*>(&g_AhT[0][0]) + r * (MAXK * 2) + j * 16);
    }
    for (int idx = tid; idx < MAXK; idx += 256)
        *reinterpret_cast<uint32_t*>(sm + OFF_SPEC + idx * 4) = g_spec[idx];

    // ---- stage x (fp32, [l][ch]) ----
    if (valid) {
        const float* xp = x + ((size_t)b * CC + wt) * LL;
#pragma unroll
        for (int l = 0; l < LL; ++l)
            *reinterpret_cast<float*>(xsm + l * XS_ROW + wt * 4) = xp[l];
    } else {
#pragma unroll
        for (int l = 0; l < LL; ++l)
            *reinterpret_cast<float*>(xsm + l * XS_ROW + wt * 4) = 0.f;
    }

    // ---- effective weights ----
    float yr[EE];
#pragma unroll
    for (int e = 0; e < EE; ++e) yr[e] = valid ? __ldg(y + (size_t)b * EE + e) : 0.f;

#pragma unroll
    for (int k = 0; k < PP3; ++k) {
        float s = 0.f;
#pragma unroll
        for (int e = 0; e < EE; ++e)
            s = fmaf(yr[e], __ldg(w3 + (size_t)(e * PP3 + k) * CC + wt), s);
        *reinterpret_cast<float*>(w3f + k * W3_ROW + wt * 4) = s;
    }
    *reinterpret_cast<float*>(w3f + 23 * W3_ROW + wt * 4) = 0.f;   // pad col
#pragma unroll
    for (int k = 0; k < PP2; ++k) {
        float s = 0.f;
#pragma unroll
        for (int e = 0; e < EE; ++e)
            s = fmaf(yr[e], __ldg(w2 + (size_t)(e * PP2 + k) * CC + wt), s);
        *reinterpret_cast<__half*>(w2h + k * 256 + wt * 2) = __float2half(s);
    }
    {
        float s = 0.f;
#pragma unroll
        for (int e = 0; e < EE; ++e)
            s = fmaf(yr[e], __ldg(w1 + (size_t)e * CC + wt), s);
        w1f[wt] = s;
    }
    __syncthreads();

    // ---- U2 + U1 scalar terms for channel wt ----
    {
        float o = 0.f;
        for (int e = 0; e < n2; ++e) {
            uint2 E = __ldg(&g_e2[e]);
            const int ww = E.x & 255, xx = (E.x >> 8) & 255, kk = E.x >> 16;
            float xw = *reinterpret_cast<const float*>(xsm + ww * XS_ROW + wt * 4)
                     * *reinterpret_cast<const float*>(xsm + xx * XS_ROW + wt * 4);
            float wv = __half2float(*reinterpret_cast<const __half*>(w2h + kk * 256 + wt * 2));
            o = fmaf(__uint_as_float(E.y) * wv, xw, o);
        }
        float d = 0.f;
#pragma unroll
        for (int l = 0; l < LL; ++l)
            d = fmaf(__ldg(U1 + l), *reinterpret_cast<const float*>(xsm + l * XS_ROW + wt * 4), d);
        o = fmaf(w1f[wt], d, o);
        outs[wt] = o;
    }

    // ---- GEMM main loop ----
    const int lane = tid & 31;
    const int wm   = (tid >> 5) & 3;          // warp within node
    const int g    = lane >> 2;
    const int t4   = lane & 3;

    float acc[2][3][4];
#pragma unroll
    for (int mt = 0; mt < 2; ++mt)
#pragma unroll
        for (int nt = 0; nt < 3; ++nt)
#pragma unroll
            for (int q = 0; q < 4; ++q) acc[mt][nt][q] = 0.f;

    const int nchunks = KP >> 4;
    for (int c = 0; c < nchunks; ++c) {
        const int  kb  = c * 16;
        char* buf = msm + (c & 1) * MS_BUF;

        // generate monomial chunk: m[k][ch] fp16, thread does 4 (k, 4ch) tasks
#pragma unroll
        for (int j = 0; j < 4; ++j) {
            const int task = j * 128 + wt;
            const int k    = task >> 5;
            const int grp  = task & 31;
            const uint32_t sp = *reinterpret_cast<const uint32_t*>(sm + OFF_SPEC + (kb + k) * 4);
            const int a  = sp & 255, b2 = (sp >> 8) & 255, c3 = (sp >> 16) & 255;
            float4 xa = *reinterpret_cast<const float4*>(xsm + a  * XS_ROW + grp * 16);
            float4 xb = *reinterpret_cast<const float4*>(xsm + b2 * XS_ROW + grp * 16);
            float4 xc = *reinterpret_cast<const float4*>(xsm + c3 * XS_ROW + grp * 16);
            *reinterpret_cast<uint2*>(buf + k * MS_ROW + grp * 8) =
                f4_to_h4(f4mul(f4mul(xa, xb), xc));
        }
        __syncthreads();

        // A fragments (2 m-tiles)
        uint32_t afr[2][4];
#pragma unroll
        for (int mt = 0; mt < 2; ++mt) {
            const int mb = wm * 32 + mt * 16 + g;
            const char* r0 = buf + (2 * t4)     * MS_ROW;
            const char* r1 = buf + (2 * t4 + 1) * MS_ROW;
            const char* r8 = buf + (2 * t4 + 8) * MS_ROW;
            const char* r9 = buf + (2 * t4 + 9) * MS_ROW;
            afr[mt][0] = pk16(*reinterpret_cast<const unsigned short*>(r0 + mb * 2),
                              *reinterpret_cast<const unsigned short*>(r1 + mb * 2));
            afr[mt][1] = pk16(*reinterpret_cast<const unsigned short*>(r0 + (mb + 8) * 2),
                              *reinterpret_cast<const unsigned short*>(r1 + (mb + 8) * 2));
            afr[mt][2] = pk16(*reinterpret_cast<const unsigned short*>(r8 + mb * 2),
                              *reinterpret_cast<const unsigned short*>(r9 + mb * 2));
            afr[mt][3] = pk16(*reinterpret_cast<const unsigned short*>(r8 + (mb + 8) * 2),
                              *reinterpret_cast<const unsigned short*>(r9 + (mb + 8) * 2));
        }
        // B fragments + mma (3 n-tiles)
#pragma unroll
        for (int nt = 0; nt < 3; ++nt) {
            const char* brow = sm + OFF_AHT + (nt * 8 + g) * AHT_ROW;
            uint32_t b0 = *reinterpret_cast<const uint32_t*>(brow + (kb + 2 * t4) * 2);
            uint32_t b1 = *reinterpret_cast<const uint32_t*>(brow + (kb + 2 * t4 + 8) * 2);
            MMA16816(acc[0][nt][0], acc[0][nt][1], acc[0][nt][2], acc[0][nt][3],
                     afr[0][0], afr[0][1], afr[0][2], afr[0][3], b0, b1);
            MMA16816(acc[1][nt][0], acc[1][nt][1], acc[1][nt][2], acc[1][nt][3],
                     afr[1][0], afr[1][1], afr[1][2], afr[1][3], b0, b1);
        }
    }

    // ---- epilogue: out[ch] = outs[ch] + sum_k W3[k][ch] * Q[ch][k] ----
#pragma unroll
    for (int mt = 0; mt < 2; ++mt) {
#pragma unroll
        for (int h = 0; h < 2; ++h) {
            const int ch = wm * 32 + mt * 16 + g + h * 8;
            float S = 0.f;
#pragma unroll
            for (int nt = 0; nt < 3; ++nt) {
                const int k0 = nt * 8 + 2 * t4;
                float wv0 = *reinterpret_cast<const float*>(w3f + k0 * W3_ROW + ch * 4);
                float wv1 = *reinterpret_cast<const float*>(w3f + (k0 + 1) * W3_ROW + ch * 4);
                S = fmaf(acc[mt][nt][h * 2 + 0], wv0, S);
                S = fmaf(acc[mt][nt][h * 2 + 1], wv1, S);
            }
            S += __shfl_xor_sync(0xffffffffu, S, 1);
            S += __shfl_xor_sync(0xffffffffu, S, 2);
            if (t4 == 0 && valid)
                out[(size_t)b * CC + ch] = S + outs[ch];
        }
    }
}

// ---------------------------------------------------------------------------
extern "C" void kernel_launch(void* const* d_in, const int* in_sizes, int n_in,
                              void* d_out, int out_size)
{
    const float* x  = (const float*)d_in[0];   // [B,C,L]
    const float* y  = (const float*)d_in[1];   // [B,E]
    const float* U3 = (const float*)d_in[2];   // [16,16,16,23]
    const float* U2 = (const float*)d_in[3];   // [16,16,4]
    const float* U1 = (const float*)d_in[4];   // [16,1]
    const float* w3 = (const float*)d_in[5];   // [10,23,128]
    const float* w2 = (const float*)d_in[6];   // [10,4,128]
    const float* w1 = (const float*)d_in[7];   // [10,1,128]
    float* out = (float*)d_out;

    const int B = in_sizes[0] / (CC * LL);

    build_tables_kernel<<<1, 1024>>>(U3, U2);

    cudaFuncSetAttribute(sym_gemm_kernel,
                         cudaFuncAttributeMaxDynamicSharedMemorySize, SH_BYTES);
    const int grid = (B + 1) / 2;
    sym_gemm_kernel<<<grid, 256, SH_BYTES>>>(x, y, w3, w2, w1, U1, out, B);
}

// round 12
// speedup vs baseline: 6.4402x; 1.5326x over previous
#include <cuda_runtime.h>
#include <cuda_fp16.h>
#include <cstdint>

// ---------------------------------------------------------------------------
// SymmetricContraction via monomial GEMM (fp16 in / fp32 accum mma.m16n8k16).
// out[b,c] = sum_k W3[k]*Q3[k] + U2/U1 scalar terms
//   Q3[b,c,k] = sum_T A[T,k] * m[b,c,T],  m = x_a x_b x_c over sorted triples
// Block = 3 nodes x 128 threads. Packed-pair A layout: one LDS.32 per A reg.
// ---------------------------------------------------------------------------

#define CC   128
#define LL   16
#define EE   10
#define PP3  23
#define PP2  4
#define MAXK 832        // sorted triples <= 816, padded to mult of 16
#define NPAD 24         // GEMM N: 23 paths + 1 zero col
#define NNODES 3
#define THREADS (NNODES*128)

// ---- device globals (no allocation allowed) ----
__device__ float    g_Af[MAXK][NPAD];     // fp32 A accumulation
__device__ __half   g_AhT[NPAD][MAXK];    // A transposed, fp16 (B operand src)
__device__ uint32_t g_spec[MAXK];         // a | b<<8 | c<<16
__device__ uint2    g_e2[1040];           // U2: (w|x<<8|k<<16, f32 v)
__device__ unsigned g_K;                  // padded K
__device__ unsigned g_n2;

// ---------------------------------------------------------------------------
__device__ __forceinline__ int block_exscan_1024(int cnt, int t, int* warp_sums, int* total)
{
    __syncthreads();
    const int lane = t & 31, wid = t >> 5;
    int inc = cnt;
#pragma unroll
    for (int d = 1; d < 32; d <<= 1) {
        int n = __shfl_up_sync(0xffffffffu, inc, d);
        if (lane >= d) inc += n;
    }
    if (lane == 31) warp_sums[wid] = inc;
    __syncthreads();
    if (wid == 0) {
        int v = warp_sums[lane];
#pragma unroll
        for (int d = 1; d < 32; d <<= 1) {
            int n = __shfl_up_sync(0xffffffffu, v, d);
            if (lane >= d) v += n;
        }
        warp_sums[lane] = v;
    }
    __syncthreads();
    *total = warp_sums[31];
    return inc - cnt + (wid ? warp_sums[wid - 1] : 0);
}

__device__ __forceinline__ void sort3(int& a, int& b, int& c)
{
    int t;
    if (a > b) { t = a; a = b; b = t; }
    if (b > c) { t = b; b = c; c = t; }
    if (a > b) { t = a; a = b; b = t; }
}

// ---------------------------------------------------------------------------
// Build tables (unchanged from R10, which verified correct).
// ---------------------------------------------------------------------------
__global__ __launch_bounds__(1024)
void build_tables_kernel(const float* __restrict__ U3, const float* __restrict__ U2)
{
    __shared__ int            warp_sums[32];
    __shared__ unsigned char  used3[4096];
    __shared__ unsigned short cellid[4096];
    const int t = threadIdx.x;

    for (int idx = t; idx < MAXK * NPAD; idx += 1024)
        (&g_Af[0][0])[idx] = 0.f;
    for (int idx = t; idx < MAXK; idx += 1024)
        g_spec[idx] = 0u;
#pragma unroll
    for (int j = 0; j < 4; ++j) used3[t * 4 + j] = 0;
    __syncthreads();

    const int base = t * 92;
    const int w  = t >> 6;
    const int x2 = (t >> 2) & 15;
#pragma unroll
    for (int g = 0; g < 4; ++g) {
        const int i = (t & 3) * 4 + g;
        for (int k = 0; k < PP3; ++k) {
            if (U3[base + g * PP3 + k] != 0.f) {
                int a = w, b = x2, c = i;
                sort3(a, b, c);
                used3[a * 256 + b * 16 + c] = 1;
            }
        }
    }
    __syncthreads();

    int cnt = 0;
#pragma unroll
    for (int j = 0; j < 4; ++j) cnt += used3[t * 4 + j];
    int K3;
    int pos = block_exscan_1024(cnt, t, warp_sums, &K3);
#pragma unroll
    for (int j = 0; j < 4; ++j) {
        const int cell = t * 4 + j;
        if (used3[cell]) {
            cellid[cell] = (unsigned short)pos;
            const int a = cell >> 8, b = (cell >> 4) & 15, c = cell & 15;
            g_spec[pos] = (uint32_t)a | ((uint32_t)b << 8) | ((uint32_t)c << 16);
            ++pos;
        }
    }
    if (t == 0) g_K = (unsigned)((K3 + 15) & ~15);
    __syncthreads();

#pragma unroll
    for (int g = 0; g < 4; ++g) {
        const int i = (t & 3) * 4 + g;
        for (int k = 0; k < PP3; ++k) {
            float v = U3[base + g * PP3 + k];
            if (v != 0.f) {
                int a = w, b = x2, c = i;
                sort3(a, b, c);
                atomicAdd(&g_Af[cellid[a * 256 + b * 16 + c]][k], v);
            }
        }
    }

    int cnt2 = 0;
    if (t < 256) {
#pragma unroll
        for (int k = 0; k < PP2; ++k) cnt2 += (U2[t * PP2 + k] != 0.f);
    }
    int total2;
    int p2 = block_exscan_1024(cnt2, t, warp_sums, &total2);
    if (t < 256) {
        const uint32_t wx = (uint32_t)(t >> 4) | ((uint32_t)(t & 15) << 8);
        for (int k = 0; k < PP2; ++k) {
            float v = U2[t * PP2 + k];
            if (v != 0.f) {
                g_e2[p2] = make_uint2(wx | ((uint32_t)k << 16), __float_as_uint(v));
                ++p2;
            }
        }
    }
    if (t == 0) g_n2 = (unsigned)total2;

    __threadfence();
    __syncthreads();

    for (int idx = t; idx < NPAD * MAXK; idx += 1024) {
        const int n = idx / MAXK, m = idx % MAXK;
        g_AhT[n][m] = __float2half(g_Af[m][n]);
    }
}

// ---------------------------------------------------------------------------
#define MMA16816(d0,d1,d2,d3,a0,a1,a2,a3,b0,b1)                         \
    asm volatile("mma.sync.aligned.m16n8k16.row.col.f32.f16.f16.f32 "   \
        "{%0,%1,%2,%3}, {%4,%5,%6,%7}, {%8,%9}, {%0,%1,%2,%3};"         \
        : "+f"(d0), "+f"(d1), "+f"(d2), "+f"(d3)                        \
        : "r"(a0), "r"(a1), "r"(a2), "r"(a3), "r"(b0), "r"(b1))

__device__ __forceinline__ __half2 u2h2(uint32_t u) { return *reinterpret_cast<__half2*>(&u); }

// monomial for 4 channels, fp16: m = xa*xb*xc
__device__ __forceinline__ uint2 mono4(const char* xh, uint32_t sp, int goff, int XHR)
{
    uint2 xa = *reinterpret_cast<const uint2*>(xh + (sp & 255u)        * XHR + goff);
    uint2 xb = *reinterpret_cast<const uint2*>(xh + ((sp >> 8) & 255u) * XHR + goff);
    uint2 xc = *reinterpret_cast<const uint2*>(xh + ((sp >> 16) & 255u)* XHR + goff);
    __half2 p0 = __hmul2(__hmul2(u2h2(xa.x), u2h2(xb.x)), u2h2(xc.x));
    __half2 p1 = __hmul2(__hmul2(u2h2(xa.y), u2h2(xb.y)), u2h2(xc.y));
    uint2 r;
    r.x = *reinterpret_cast<uint32_t*>(&p0);
    r.y = *reinterpret_cast<uint32_t*>(&p1);
    return r;
}

// ---------------------------------------------------------------------------
// smem layout (bytes), block = 3 nodes x 128 threads
// mp row = 128 channels * half2 = 512 B data + 32 B pad = 544 B
// (MP_ROW/4 = 136 ≡ 8 mod 32 -> A-frag banks 8*t4+g all distinct)
// ---------------------------------------------------------------------------
#define AHT_ROW   1680                        // 1664 data + 16 pad
#define OFF_AHT   0
#define OFF_SPEC  (NPAD * AHT_ROW)            // 40320
#define OFF_NODE  (OFF_SPEC + MAXK * 4)       // 43648
#define XH_ROW    272                         // 128 fp16 + 16 pad
#define MP_ROW    544
#define MP_BUF    (8 * MP_ROW)                // 4352
#define W3H_ROW   264                         // 128 fp16 + 8 pad
#define NB_XH     0
#define NB_MP     (NB_XH + LL * XH_ROW)       // 4352
#define NB_W3     (NB_MP + 2 * MP_BUF)        // 13056
#define NB_W2     (NB_W3 + NPAD * W3H_ROW)    // 19392
#define NB_W1     (NB_W2 + PP2 * 256)         // 20416
#define NB_OUT    (NB_W1 + 512)               // 20928
#define NODE_BYTES (NB_OUT + 512)             // 21440
#define SH_BYTES  (OFF_NODE + NNODES * NODE_BYTES)  // 107968

__global__ __launch_bounds__(THREADS, 2)
void sym_gemm_kernel(const float* __restrict__ x,
                     const float* __restrict__ y,
                     const float* __restrict__ w3,
                     const float* __restrict__ w2,
                     const float* __restrict__ w1,
                     const float* __restrict__ U1,
                     float* __restrict__ out,
                     int B)
{
    extern __shared__ char sm[];
    const int tid  = threadIdx.x;
    const int node = tid >> 7;
    const int wt   = tid & 127;               // channel for setup phases
    const int b    = blockIdx.x * NNODES + node;
    const bool valid = (b < B);

    char* nb  = sm + OFF_NODE + node * NODE_BYTES;
    char* xh  = nb + NB_XH;
    char* msm = nb + NB_MP;
    char* w3h = nb + NB_W3;
    char* w2h = nb + NB_W2;
    float* w1f  = reinterpret_cast<float*>(nb + NB_W1);
    float* outs = reinterpret_cast<float*>(nb + NB_OUT);

    const int KP = (int)g_K;
    const int n2 = (int)g_n2;

    // ---- copy AhT + spec into smem (all threads) ----
    for (int idx = tid; idx < NPAD * 104; idx += THREADS) {
        const int r = idx / 104, j = idx % 104;
        *reinterpret_cast<uint4*>(sm + OFF_AHT + r * AHT_ROW + j * 16) =
            *reinterpret_cast<const uint4*>(reinterpret_cast<const char*>(&g_AhT[0][0]) + r * (MAXK * 2) + j * 16);
    }
    for (int idx = tid; idx < MAXK; idx += THREADS)
        *reinterpret_cast<uint32_t*>(sm + OFF_SPEC + idx * 4) = g_spec[idx];

    // ---- stage x as fp16 [l][ch] ----
    if (valid) {
        const float4* xp = reinterpret_cast<const float4*>(x + ((size_t)b * CC + wt) * LL);
#pragma unroll
        for (int q = 0; q < 4; ++q) {
            float4 r = xp[q];
            *reinterpret_cast<__half*>(xh + (4 * q + 0) * XH_ROW + wt * 2) = __float2half(r.x);
            *reinterpret_cast<__half*>(xh + (4 * q + 1) * XH_ROW + wt * 2) = __float2half(r.y);
            *reinterpret_cast<__half*>(xh + (4 * q + 2) * XH_ROW + wt * 2) = __float2half(r.z);
            *reinterpret_cast<__half*>(xh + (4 * q + 3) * XH_ROW + wt * 2) = __float2half(r.w);
        }
    } else {
#pragma unroll
        for (int l = 0; l < LL; ++l)
            *reinterpret_cast<__half*>(xh + l * XH_ROW + wt * 2) = __float2half(0.f);
    }

    // ---- effective weights ----
    float yr[EE];
#pragma unroll
    for (int e = 0; e < EE; ++e) yr[e] = valid ? __ldg(y + (size_t)b * EE + e) : 0.f;

#pragma unroll
    for (int k = 0; k < PP3; ++k) {
        float s = 0.f;
#pragma unroll
        for (int e = 0; e < EE; ++e)
            s = fmaf(yr[e], __ldg(w3 + (size_t)(e * PP3 + k) * CC + wt), s);
        *reinterpret_cast<__half*>(w3h + k * W3H_ROW + wt * 2) = __float2half(s);
    }
    *reinterpret_cast<__half*>(w3h + 23 * W3H_ROW + wt * 2) = __float2half(0.f);  // pad col
#pragma unroll
    for (int k = 0; k < PP2; ++k) {
        float s = 0.f;
#pragma unroll
        for (int e = 0; e < EE; ++e)
            s = fmaf(yr[e], __ldg(w2 + (size_t)(e * PP2 + k) * CC + wt), s);
        *reinterpret_cast<__half*>(w2h + k * 256 + wt * 2) = __float2half(s);
    }
    {
        float s = 0.f;
#pragma unroll
        for (int e = 0; e < EE; ++e)
            s = fmaf(yr[e], __ldg(w1 + (size_t)e * CC + wt), s);
        w1f[wt] = s;
    }

    // ---- U2 + U1 scalar terms (own-channel data only: no sync needed) ----
    {
        float o = 0.f;
        for (int e = 0; e < n2; ++e) {
            uint2 E = __ldg(&g_e2[e]);
            const int ww = E.x & 255, xx = (E.x >> 8) & 255, kk = E.x >> 16;
            float xw = __half2float(*reinterpret_cast<const __half*>(xh + ww * XH_ROW + wt * 2))
                     * __half2float(*reinterpret_cast<const __half*>(xh + xx * XH_ROW + wt * 2));
            float wv = __half2float(*reinterpret_cast<const __half*>(w2h + kk * 256 + wt * 2));
            o = fmaf(__uint_as_float(E.y) * wv, xw, o);
        }
        float d = 0.f;
#pragma unroll
        for (int l = 0; l < LL; ++l)
            d = fmaf(__ldg(U1 + l),
                     __half2float(*reinterpret_cast<const __half*>(xh + l * XH_ROW + wt * 2)), d);
        o = fmaf(w1f[wt], d, o);
        outs[wt] = o;
    }
    __syncthreads();

    // ---- GEMM main loop ----
    const int lane = tid & 31;
    const int wm   = (tid >> 5) & 3;          // warp within node
    const int g    = lane >> 2;
    const int t4   = lane & 3;
    const int grp  = lane;                    // gen channel-group = lane

    // precomputed bases
    const char* fb  = msm + t4 * MP_ROW + (wm * 32 + g) * 4;   // A-frag base
    const char* bb  = sm + OFF_AHT + g * AHT_ROW + t4 * 4;     // B-frag base
    char*       gb  = msm + grp * 16;                          // gen write base

    float acc[2][3][4];
#pragma unroll
    for (int mt = 0; mt < 2; ++mt)
#pragma unroll
        for (int nt = 0; nt < 3; ++nt)
#pragma unroll
            for (int q = 0; q < 4; ++q) acc[mt][nt][q] = 0.f;

    const int nchunks = KP >> 4;
    for (int c = 0; c < nchunks; ++c) {
        const int kb = c * 16;
        const int po = (c & 1) * MP_BUF;

        // gen: 2 tasks/thread -> mp[k2][ch] = half2(m[2k2][ch], m[2k2+1][ch])
#pragma unroll
        for (int j = 0; j < 2; ++j) {
            const int k2 = j * 4 + wm;        // task = j*128 + wt; k2 = task>>5
            const uint32_t spA = *reinterpret_cast<const uint32_t*>(sm + OFF_SPEC + (kb + 2 * k2) * 4);
            const uint32_t spB = *reinterpret_cast<const uint32_t*>(sm + OFF_SPEC + (kb + 2 * k2 + 1) * 4);
            uint2 mA = mono4(xh, spA, grp * 8, XH_ROW);
            uint2 mB = mono4(xh, spB, grp * 8, XH_ROW);
            uint4 wv;
            wv.x = __byte_perm(mA.x, mB.x, 0x5410);
            wv.y = __byte_perm(mA.x, mB.x, 0x7632);
            wv.z = __byte_perm(mA.y, mB.y, 0x5410);
            wv.w = __byte_perm(mA.y, mB.y, 0x7632);
            *reinterpret_cast<uint4*>(gb + po + k2 * MP_ROW) = wv;
        }
        __syncthreads();

        // A fragments: one LDS.32 per register
        uint32_t afr[2][4];
#pragma unroll
        for (int mt = 0; mt < 2; ++mt) {
            const char* fa = fb + po + mt * 64;
            afr[mt][0] = *reinterpret_cast<const uint32_t*>(fa);
            afr[mt][1] = *reinterpret_cast<const uint32_t*>(fa + 32);
            afr[mt][2] = *reinterpret_cast<const uint32_t*>(fa + 4 * MP_ROW);
            afr[mt][3] = *reinterpret_cast<const uint32_t*>(fa + 4 * MP_ROW + 32);
        }
        // B fragments + mma
#pragma unroll
        for (int nt = 0; nt < 3; ++nt) {
            const char* bp = bb + nt * (8 * AHT_ROW) + kb * 2;
            uint32_t b0 = *reinterpret_cast<const uint32_t*>(bp);
            uint32_t b1 = *reinterpret_cast<const uint32_t*>(bp + 16);
            MMA16816(acc[0][nt][0], acc[0][nt][1], acc[0][nt][2], acc[0][nt][3],
                     afr[0][0], afr[0][1], afr[0][2], afr[0][3], b0, b1);
            MMA16816(acc[1][nt][0], acc[1][nt][1], acc[1][nt][2], acc[1][nt][3],
                     afr[1][0], afr[1][1], afr[1][2], afr[1][3], b0, b1);
        }
    }

    // ---- epilogue: out[ch] = outs[ch] + sum_k W3[k][ch] * Q[ch][k] ----
#pragma unroll
    for (int mt = 0; mt < 2; ++mt) {
#pragma unroll
        for (int h = 0; h < 2; ++h) {
            const int ch = wm * 32 + mt * 16 + g + h * 8;
            float S = 0.f;
#pragma unroll
            for (int nt = 0; nt < 3; ++nt) {
                const int k0 = nt * 8 + 2 * t4;
                float wv0 = __half2float(*reinterpret_cast<const __half*>(w3h + k0 * W3H_ROW + ch * 2));
                float wv1 = __half2float(*reinterpret_cast<const __half*>(w3h + (k0 + 1) * W3H_ROW + ch * 2));
                S = fmaf(acc[mt][nt][h * 2 + 0], wv0, S);
                S = fmaf(acc[mt][nt][h * 2 + 1], wv1, S);
            }
            S += __shfl_xor_sync(0xffffffffu, S, 1);
            S += __shfl_xor_sync(0xffffffffu, S, 2);
            if (t4 == 0 && valid)
                out[(size_t)b * CC + ch] = S + outs[ch];
        }
    }
}

// ---------------------------------------------------------------------------
extern "C" void kernel_launch(void* const* d_in, const int* in_sizes, int n_in,
                              void* d_out, int out_size)
{
    const float* x  = (const float*)d_in[0];   // [B,C,L]
    const float* y  = (const float*)d_in[1];   // [B,E]
    const float* U3 = (const float*)d_in[2];   // [16,16,16,23]
    const float* U2 = (const float*)d_in[3];   // [16,16,4]
    const float* U1 = (const float*)d_in[4];   // [16,1]
    const float* w3 = (const float*)d_in[5];   // [10,23,128]
    const float* w2 = (const float*)d_in[6];   // [10,4,128]
    const float* w1 = (const float*)d_in[7];   // [10,1,128]
    float* out = (float*)d_out;

    const int B = in_sizes[0] / (CC * LL);

    build_tables_kernel<<<1, 1024>>>(U3, U2);

    cudaFuncSetAttribute(sym_gemm_kernel,
                         cudaFuncAttributeMaxDynamicSharedMemorySize, SH_BYTES);
    const int grid = (B + NNODES - 1) / NNODES;
    sym_gemm_kernel<<<grid, THREADS, SH_BYTES>>>(x, y, w3, w2, w1, U1, out, B);
}

// round 13
// speedup vs baseline: 7.7772x; 1.2076x over previous
#include <cuda_runtime.h>
#include <cuda_fp16.h>
#include <cstdint>

// ---------------------------------------------------------------------------
// SymmetricContraction via monomial GEMM (fp16 in / fp32 accum mma.m16n8k16).
// out[b,c] = sum_k W3[k]*Q3[k] + U2/U1 scalar terms
//   Q3[b,c,k] = sum_T A[T,k] * m[b,c,T],  m = x_a x_b x_c over sorted triples
// Triples grouped by (a,b) pair, padded to even runs -> gen tasks always
// share the (a,b) product. A-frags via ldmatrix.x4.trans. Build parallelized.
// ---------------------------------------------------------------------------

#define CC   128
#define LL   16
#define EE   10
#define PP3  23
#define PP2  4
#define NU3  (16*16*16*23)   // 94208
#define MAXK 960             // sorted triples + pair padding, mult of 16
#define NPAD 24              // GEMM N: 23 paths + 1 zero col
#define NNODES 3
#define THREADS (NNODES*128)

// ---- device globals (no allocation allowed) ----
__device__ float          g_Af[MAXK][NPAD];   // fp32 A accumulation
__device__ __half         g_AhT[NPAD][MAXK];  // A transposed, fp16
__device__ uint32_t       g_spec[MAXK];       // a | b<<8 | c<<16
__device__ unsigned short g_cellid[4096];     // sorted-cell -> slot
__device__ uint2          g_e2[1040];         // U2: (w|x<<8|k<<16, f32 v)
__device__ unsigned       g_K;                // padded K
__device__ unsigned       g_n2;

// ---------------------------------------------------------------------------
__device__ __forceinline__ int block_exscan_1024(int cnt, int t, int* warp_sums, int* total)
{
    __syncthreads();
    const int lane = t & 31, wid = t >> 5;
    int inc = cnt;
#pragma unroll
    for (int d = 1; d < 32; d <<= 1) {
        int n = __shfl_up_sync(0xffffffffu, inc, d);
        if (lane >= d) inc += n;
    }
    if (lane == 31) warp_sums[wid] = inc;
    __syncthreads();
    if (wid == 0) {
        int v = warp_sums[lane];
#pragma unroll
        for (int d = 1; d < 32; d <<= 1) {
            int n = __shfl_up_sync(0xffffffffu, v, d);
            if (lane >= d) v += n;
        }
        warp_sums[lane] = v;
    }
    __syncthreads();
    *total = warp_sums[31];
    return inc - cnt + (wid ? warp_sums[wid - 1] : 0);
}

__device__ __forceinline__ void sort3(int& a, int& b, int& c)
{
    int t;
    if (a > b) { t = a; a = b; b = t; }
    if (b > c) { t = b; b = c; c = t; }
    if (a > b) { t = a; a = b; b = t; }
}

// ---------------------------------------------------------------------------
// b0: single block. used3 bitmap -> pair-even slotting -> spec/cellid. U2 list.
// ---------------------------------------------------------------------------
__global__ __launch_bounds__(1024)
void build_b0(const float* __restrict__ U3, const float* __restrict__ U2)
{
    __shared__ int           warp_sums[32];
    __shared__ unsigned char used3[4096];
    const int t = threadIdx.x;

    for (int idx = t; idx < MAXK; idx += 1024) g_spec[idx] = 0u;
#pragma unroll
    for (int j = 0; j < 4; ++j) used3[t * 4 + j] = 0;
    __syncthreads();

    // mark used sorted triples
    const int base = t * 92;
    const int w  = t >> 6;
    const int x2 = (t >> 2) & 15;
#pragma unroll
    for (int g = 0; g < 4; ++g) {
        const int i = (t & 3) * 4 + g;
        for (int k = 0; k < PP3; ++k) {
            if (U3[base + g * PP3 + k] != 0.f) {
                int a = w, b = x2, c = i;
                sort3(a, b, c);
                used3[a * 256 + b * 16 + c] = 1;
            }
        }
    }
    __syncthreads();

    // pair-even slotting: pair (a,b) with a<=b owns even # of slots
    int a = t >> 4, b = t & 15;
    int cnt = 0;
    if (t < 256 && a <= b)
        for (int c = b; c < 16; ++c) cnt += used3[a * 256 + b * 16 + c];
    int slots = (cnt + 1) & ~1;
    int total;
    int basep = block_exscan_1024((t < 256) ? slots : 0, t, warp_sums, &total);
    if (t < 256 && cnt > 0) {
        int pos = basep;
        for (int c = b; c < 16; ++c) {
            const int cell = a * 256 + b * 16 + c;
            if (used3[cell]) {
                g_cellid[cell] = (unsigned short)pos;
                g_spec[pos] = (uint32_t)a | ((uint32_t)b << 8) | ((uint32_t)c << 16);
                ++pos;
            }
        }
        if (cnt & 1)   // dummy slot: same (a,b), A row stays zero
            g_spec[pos] = (uint32_t)a | ((uint32_t)b << 8) | (15u << 16);
    }
    if (t == 0) g_K = (unsigned)((total + 15) & ~15);

    // ---- U2 list ----
    int cnt2 = 0;
    if (t < 256) {
#pragma unroll
        for (int k = 0; k < PP2; ++k) cnt2 += (U2[t * PP2 + k] != 0.f);
    }
    int total2;
    int p2 = block_exscan_1024(cnt2, t, warp_sums, &total2);
    if (t < 256) {
        const uint32_t wx = (uint32_t)(t >> 4) | ((uint32_t)(t & 15) << 8);
        for (int k = 0; k < PP2; ++k) {
            float v = U2[t * PP2 + k];
            if (v != 0.f) {
                g_e2[p2] = make_uint2(wx | ((uint32_t)k << 16), __float_as_uint(v));
                ++p2;
            }
        }
    }
    if (t == 0) g_n2 = (unsigned)total2;
}

// b1: zero A accumulator (grid-wide)
__global__ void build_b1()
{
    int i = blockIdx.x * blockDim.x + threadIdx.x;
    if (i < MAXK * NPAD) (&g_Af[0][0])[i] = 0.f;
}

// b2: accumulate A (grid-wide, one thread per U3 element)
__global__ void build_b2(const float* __restrict__ U3)
{
    int i = blockIdx.x * blockDim.x + threadIdx.x;
    if (i >= NU3) return;
    float v = U3[i];
    if (v == 0.f) return;
    int k = i % PP3;
    int r = i / PP3;
    int a = r >> 8, b = (r >> 4) & 15, c = r & 15;
    sort3(a, b, c);
    atomicAdd(&g_Af[g_cellid[a * 256 + b * 16 + c]][k], v);
}

// b3: convert to transposed fp16 (grid-wide)
__global__ void build_b3()
{
    int i = blockIdx.x * blockDim.x + threadIdx.x;
    if (i >= NPAD * MAXK) return;
    int n = i / MAXK, m = i % MAXK;
    g_AhT[n][m] = __float2half(g_Af[m][n]);
}

// ---------------------------------------------------------------------------
#define MMA16816(d0,d1,d2,d3,a0,a1,a2,a3,b0,b1)                         \
    asm volatile("mma.sync.aligned.m16n8k16.row.col.f32.f16.f16.f32 "   \
        "{%0,%1,%2,%3}, {%4,%5,%6,%7}, {%8,%9}, {%0,%1,%2,%3};"         \
        : "+f"(d0), "+f"(d1), "+f"(d2), "+f"(d3)                        \
        : "r"(a0), "r"(a1), "r"(a2), "r"(a3), "r"(b0), "r"(b1))

__device__ __forceinline__ __half2 u2h2(uint32_t u) { return *reinterpret_cast<__half2*>(&u); }
__device__ __forceinline__ uint32_t h2u(__half2 h) { return *reinterpret_cast<uint32_t*>(&h); }

__device__ __forceinline__ void ldsm_x4_trans(uint32_t* r, uint32_t saddr)
{
    asm volatile("ldmatrix.sync.aligned.m8n8.x4.trans.shared.b16 {%0,%1,%2,%3}, [%4];"
        : "=r"(r[0]), "=r"(r[1]), "=r"(r[2]), "=r"(r[3]) : "r"(saddr));
}

// ---------------------------------------------------------------------------
// smem layout (bytes), block = 3 nodes x 128 threads
// mp natural [k][ch]: row = 128 ch * fp16 = 256B + 16 pad = 272
// (row stride 68 words ≡ 4 mod 32 -> each ldmatrix 8-row phase hits 32 banks)
// ---------------------------------------------------------------------------
#define AHT_ROW   1936                        // 1920 data + 16 pad
#define OFF_AHT   0
#define OFF_SPEC  (NPAD * AHT_ROW)            // 46464
#define OFF_NODE  (OFF_SPEC + MAXK * 4)       // 50304
#define XH_ROW    272                         // 128 fp16 + 16 pad
#define MP_ROW    272
#define MP_BUF    (16 * MP_ROW)               // 4352
#define W3H_ROW   264                         // 128 fp16 + 8 pad
#define NB_XH     0
#define NB_MP     (NB_XH + LL * XH_ROW)       // 4352
#define NB_W3     (NB_MP + 2 * MP_BUF)        // 13056
#define NB_W2     (NB_W3 + NPAD * W3H_ROW)    // 19392
#define NB_W1     (NB_W2 + PP2 * 256)         // 20416
#define NB_OUT    (NB_W1 + 512)               // 20928
#define NODE_BYTES (NB_OUT + 512)             // 21440
#define SH_BYTES  (OFF_NODE + NNODES * NODE_BYTES)  // 114624

__global__ __launch_bounds__(THREADS, 2)
void sym_gemm_kernel(const float* __restrict__ x,
                     const float* __restrict__ y,
                     const float* __restrict__ w3,
                     const float* __restrict__ w2,
                     const float* __restrict__ w1,
                     const float* __restrict__ U1,
                     float* __restrict__ out,
                     int B)
{
    extern __shared__ char sm[];
    const int tid  = threadIdx.x;
    const int node = tid >> 7;
    const int wt   = tid & 127;               // channel for setup phases
    const int b    = blockIdx.x * NNODES + node;
    const bool valid = (b < B);

    char* nb  = sm + OFF_NODE + node * NODE_BYTES;
    char* xh  = nb + NB_XH;
    char* msm = nb + NB_MP;
    char* w3h = nb + NB_W3;
    char* w2h = nb + NB_W2;
    float* w1f  = reinterpret_cast<float*>(nb + NB_W1);
    float* outs = reinterpret_cast<float*>(nb + NB_OUT);

    const int KP = (int)g_K;
    const int n2 = (int)g_n2;

    // ---- copy AhT + spec into smem (all threads) ----
    for (int idx = tid; idx < NPAD * 120; idx += THREADS) {
        const int r = idx / 120, j = idx % 120;
        *reinterpret_cast<uint4*>(sm + OFF_AHT + r * AHT_ROW + j * 16) =
            *reinterpret_cast<const uint4*>(reinterpret_cast<const char*>(&g_AhT[0][0]) + r * (MAXK * 2) + j * 16);
    }
    for (int idx = tid; idx < MAXK; idx += THREADS)
        *reinterpret_cast<uint32_t*>(sm + OFF_SPEC + idx * 4) = g_spec[idx];

    // ---- stage x as fp16 [l][ch] ----
    if (valid) {
        const float4* xp = reinterpret_cast<const float4*>(x + ((size_t)b * CC + wt) * LL);
#pragma unroll
        for (int q = 0; q < 4; ++q) {
            float4 r = xp[q];
            *reinterpret_cast<__half*>(xh + (4 * q + 0) * XH_ROW + wt * 2) = __float2half(r.x);
            *reinterpret_cast<__half*>(xh + (4 * q + 1) * XH_ROW + wt * 2) = __float2half(r.y);
            *reinterpret_cast<__half*>(xh + (4 * q + 2) * XH_ROW + wt * 2) = __float2half(r.z);
            *reinterpret_cast<__half*>(xh + (4 * q + 3) * XH_ROW + wt * 2) = __float2half(r.w);
        }
    } else {
#pragma unroll
        for (int l = 0; l < LL; ++l)
            *reinterpret_cast<__half*>(xh + l * XH_ROW + wt * 2) = __float2half(0.f);
    }

    // ---- effective weights ----
    float yr[EE];
#pragma unroll
    for (int e = 0; e < EE; ++e) yr[e] = valid ? __ldg(y + (size_t)b * EE + e) : 0.f;

#pragma unroll
    for (int k = 0; k < PP3; ++k) {
        float s = 0.f;
#pragma unroll
        for (int e = 0; e < EE; ++e)
            s = fmaf(yr[e], __ldg(w3 + (size_t)(e * PP3 + k) * CC + wt), s);
        *reinterpret_cast<__half*>(w3h + k * W3H_ROW + wt * 2) = __float2half(s);
    }
    *reinterpret_cast<__half*>(w3h + 23 * W3H_ROW + wt * 2) = __float2half(0.f);  // pad col
#pragma unroll
    for (int k = 0; k < PP2; ++k) {
        float s = 0.f;
#pragma unroll
        for (int e = 0; e < EE; ++e)
            s = fmaf(yr[e], __ldg(w2 + (size_t)(e * PP2 + k) * CC + wt), s);
        *reinterpret_cast<__half*>(w2h + k * 256 + wt * 2) = __float2half(s);
    }
    {
        float s = 0.f;
#pragma unroll
        for (int e = 0; e < EE; ++e)
            s = fmaf(yr[e], __ldg(w1 + (size_t)e * CC + wt), s);
        w1f[wt] = s;
    }

    // ---- U2 + U1 scalar terms (own-channel data only: no sync needed) ----
    {
        float o = 0.f;
        for (int e = 0; e < n2; ++e) {
            uint2 E = __ldg(&g_e2[e]);
            const int ww = E.x & 255, xx = (E.x >> 8) & 255, kk = E.x >> 16;
            float xw = __half2float(*reinterpret_cast<const __half*>(xh + ww * XH_ROW + wt * 2))
                     * __half2float(*reinterpret_cast<const __half*>(xh + xx * XH_ROW + wt * 2));
            float wv = __half2float(*reinterpret_cast<const __half*>(w2h + kk * 256 + wt * 2));
            o = fmaf(__uint_as_float(E.y) * wv, xw, o);
        }
        float d = 0.f;
#pragma unroll
        for (int l = 0; l < LL; ++l)
            d = fmaf(__ldg(U1 + l),
                     __half2float(*reinterpret_cast<const __half*>(xh + l * XH_ROW + wt * 2)), d);
        o = fmaf(w1f[wt], d, o);
        outs[wt] = o;
    }
    __syncthreads();

    // ---- GEMM main loop ----
    const int lane = tid & 31;
    const int wm   = (tid >> 5) & 3;          // warp within node
    const int g    = lane >> 3;               // (unused name kept minimal below)
    const int grp  = lane;                    // gen channel-group = lane

    // ldmatrix lane address: tile tq = lane>>3, row rr = lane&7
    const int tq = lane >> 3, rr = lane & 7;
    const int krow = ((tq >> 1) & 1) * 8 + rr;
    const int chq  = (tq & 1) * 8;
    const uint32_t msm_s = (uint32_t)__cvta_generic_to_shared(msm);
    const uint32_t saddrA0 = msm_s + krow * MP_ROW + (wm * 32 + 0 * 16 + chq) * 2;
    const uint32_t saddrA1 = msm_s + krow * MP_ROW + (wm * 32 + 1 * 16 + chq) * 2;

    // B-frag base (epilogue indices need g4 = lane>>2, t4 = lane&3)
    const int g4 = lane >> 2, t4 = lane & 3;
    const char* bb = sm + OFF_AHT + g4 * AHT_ROW + t4 * 4;
    char* gb = msm + grp * 8;                 // gen write base (ch group)

    float acc[2][3][4];
#pragma unroll
    for (int mt = 0; mt < 2; ++mt)
#pragma unroll
        for (int nt = 0; nt < 3; ++nt)
#pragma unroll
            for (int q = 0; q < 4; ++q) acc[mt][nt][q] = 0.f;

    const int nchunks = KP >> 4;
    for (int c = 0; c < nchunks; ++c) {
        const int kb = c * 16;
        const int po = (c & 1) * MP_BUF;

        // gen: 2 pair-tasks/thread; adjacent k's share (a,b) by construction
#pragma unroll
        for (int j = 0; j < 2; ++j) {
            const int k2 = j * 4 + wm;
            const uint32_t spA = *reinterpret_cast<const uint32_t*>(sm + OFF_SPEC + (kb + 2 * k2) * 4);
            const uint32_t spB = *reinterpret_cast<const uint32_t*>(sm + OFF_SPEC + (kb + 2 * k2 + 1) * 4);
            const int go = grp * 8;
            uint2 xa  = *reinterpret_cast<const uint2*>(xh + (spA & 255u) * XH_ROW + go);
            uint2 xb  = *reinterpret_cast<const uint2*>(xh + ((spA >> 8) & 255u) * XH_ROW + go);
            uint2 xcA = *reinterpret_cast<const uint2*>(xh + ((spA >> 16) & 255u) * XH_ROW + go);
            uint2 xcB = *reinterpret_cast<const uint2*>(xh + ((spB >> 16) & 255u) * XH_ROW + go);
            __half2 ab0 = __hmul2(u2h2(xa.x), u2h2(xb.x));
            __half2 ab1 = __hmul2(u2h2(xa.y), u2h2(xb.y));
            uint2 mA, mB;
            mA.x = h2u(__hmul2(ab0, u2h2(xcA.x)));
            mA.y = h2u(__hmul2(ab1, u2h2(xcA.y)));
            mB.x = h2u(__hmul2(ab0, u2h2(xcB.x)));
            mB.y = h2u(__hmul2(ab1, u2h2(xcB.y)));
            *reinterpret_cast<uint2*>(gb + po + (2 * k2) * MP_ROW)     = mA;
            *reinterpret_cast<uint2*>(gb + po + (2 * k2 + 1) * MP_ROW) = mB;
        }
        __syncthreads();

        // A fragments via ldmatrix.x4.trans (stored [k][ch] = A^T)
        uint32_t afr[2][4];
        ldsm_x4_trans(afr[0], saddrA0 + po);
        ldsm_x4_trans(afr[1], saddrA1 + po);

        // B fragments + mma
#pragma unroll
        for (int nt = 0; nt < 3; ++nt) {
            const char* bp = bb + nt * (8 * AHT_ROW) + kb * 2;
            uint32_t b0 = *reinterpret_cast<const uint32_t*>(bp);
            uint32_t b1 = *reinterpret_cast<const uint32_t*>(bp + 16);
            MMA16816(acc[0][nt][0], acc[0][nt][1], acc[0][nt][2], acc[0][nt][3],
                     afr[0][0], afr[0][1], afr[0][2], afr[0][3], b0, b1);
            MMA16816(acc[1][nt][0], acc[1][nt][1], acc[1][nt][2], acc[1][nt][3],
                     afr[1][0], afr[1][1], afr[1][2], afr[1][3], b0, b1);
        }
    }

    // ---- epilogue: out[ch] = outs[ch] + sum_k W3[k][ch] * Q[ch][k] ----
#pragma unroll
    for (int mt = 0; mt < 2; ++mt) {
#pragma unroll
        for (int h = 0; h < 2; ++h) {
            const int ch = wm * 32 + mt * 16 + g4 + h * 8;
            float S = 0.f;
#pragma unroll
            for (int nt = 0; nt < 3; ++nt) {
                const int k0 = nt * 8 + 2 * t4;
                float wv0 = __half2float(*reinterpret_cast<const __half*>(w3h + k0 * W3H_ROW + ch * 2));
                float wv1 = __half2float(*reinterpret_cast<const __half*>(w3h + (k0 + 1) * W3H_ROW + ch * 2));
                S = fmaf(acc[mt][nt][h * 2 + 0], wv0, S);
                S = fmaf(acc[mt][nt][h * 2 + 1], wv1, S);
            }
            S += __shfl_xor_sync(0xffffffffu, S, 1);
            S += __shfl_xor_sync(0xffffffffu, S, 2);
            if (t4 == 0 && valid)
                out[(size_t)b * CC + ch] = S + outs[ch];
        }
    }
}

// ---------------------------------------------------------------------------
extern "C" void kernel_launch(void* const* d_in, const int* in_sizes, int n_in,
                              void* d_out, int out_size)
{
    const float* x  = (const float*)d_in[0];   // [B,C,L]
    const float* y  = (const float*)d_in[1];   // [B,E]
    const float* U3 = (const float*)d_in[2];   // [16,16,16,23]
    const float* U2 = (const float*)d_in[3];   // [16,16,4]
    const float* U1 = (const float*)d_in[4];   // [16,1]
    const float* w3 = (const float*)d_in[5];   // [10,23,128]
    const float* w2 = (const float*)d_in[6];   // [10,4,128]
    const float* w1 = (const float*)d_in[7];   // [10,1,128]
    float* out = (float*)d_out;

    const int B = in_sizes[0] / (CC * LL);

    build_b0<<<1, 1024>>>(U3, U2);
    build_b1<<<(MAXK * NPAD + 255) / 256, 256>>>();
    build_b2<<<(NU3 + 255) / 256, 256>>>(U3);
    build_b3<<<(NPAD * MAXK + 255) / 256, 256>>>();

    cudaFuncSetAttribute(sym_gemm_kernel,
                         cudaFuncAttributeMaxDynamicSharedMemorySize, SH_BYTES);
    const int grid = (B + NNODES - 1) / NNODES;
    sym_gemm_kernel<<<grid, THREADS, SH_BYTES>>>(x, y, w3, w2, w1, U1, out, B);
}

// round 14
// speedup vs baseline: 8.7863x; 1.1297x over previous
#include <cuda_runtime.h>
#include <cuda_fp16.h>
#include <cstdint>

// ---------------------------------------------------------------------------
// SymmetricContraction via monomial GEMM (fp16 in / fp32 accum mma.m16n8k16).
// out[b,c] = sum_k W3[k]*Q3[k] + U2/U1 scalar terms
//   Q3[b,c,k] = sum_T A[T,k] * m[b,c,T],  m = x_a x_b x_c over sorted triples
// A-fragments generated DIRECTLY in registers from paired-X smem layout:
// no monomial smem buffer, no ldmatrix, no barriers in the main loop.
// ---------------------------------------------------------------------------

#define CC   128
#define LL   16
#define EE   10
#define PP3  23
#define PP2  4
#define NU3  (16*16*16*23)   // 94208
#define MAXK 960             // sorted triples + pair padding, mult of 16
#define NPAD 24              // GEMM N: 23 paths + 1 zero col
#define NNODES 3
#define THREADS (NNODES*128)

// ---- device globals (no allocation allowed) ----
__device__ float          g_Af[MAXK][NPAD];   // fp32 A accumulation
__device__ __half         g_AhT[NPAD][MAXK];  // A transposed, fp16
__device__ uint32_t       g_spec[MAXK];       // a | b<<8 | c<<16
__device__ unsigned short g_cellid[4096];     // sorted-cell -> slot
__device__ uint2          g_e2[1040];         // U2: (w|x<<8|k<<16, f32 v)
__device__ unsigned       g_K;                // padded K
__device__ unsigned       g_n2;

// ---------------------------------------------------------------------------
__device__ __forceinline__ int block_exscan_1024(int cnt, int t, int* warp_sums, int* total)
{
    __syncthreads();
    const int lane = t & 31, wid = t >> 5;
    int inc = cnt;
#pragma unroll
    for (int d = 1; d < 32; d <<= 1) {
        int n = __shfl_up_sync(0xffffffffu, inc, d);
        if (lane >= d) inc += n;
    }
    if (lane == 31) warp_sums[wid] = inc;
    __syncthreads();
    if (wid == 0) {
        int v = warp_sums[lane];
#pragma unroll
        for (int d = 1; d < 32; d <<= 1) {
            int n = __shfl_up_sync(0xffffffffu, v, d);
            if (lane >= d) v += n;
        }
        warp_sums[lane] = v;
    }
    __syncthreads();
    *total = warp_sums[31];
    return inc - cnt + (wid ? warp_sums[wid - 1] : 0);
}

__device__ __forceinline__ void sort3(int& a, int& b, int& c)
{
    int t;
    if (a > b) { t = a; a = b; b = t; }
    if (b > c) { t = b; b = c; c = t; }
    if (a > b) { t = a; a = b; b = t; }
}

// ---------------------------------------------------------------------------
// b0: single block. used3 bitmap -> pair-even slotting -> spec/cellid. U2 list.
// ---------------------------------------------------------------------------
__global__ __launch_bounds__(1024)
void build_b0(const float* __restrict__ U3, const float* __restrict__ U2)
{
    __shared__ int           warp_sums[32];
    __shared__ unsigned char used3[4096];
    const int t = threadIdx.x;

    for (int idx = t; idx < MAXK; idx += 1024) g_spec[idx] = 0u;
#pragma unroll
    for (int j = 0; j < 4; ++j) used3[t * 4 + j] = 0;
    __syncthreads();

    // mark used sorted triples
    const int base = t * 92;
    const int w  = t >> 6;
    const int x2 = (t >> 2) & 15;
#pragma unroll
    for (int g = 0; g < 4; ++g) {
        const int i = (t & 3) * 4 + g;
        for (int k = 0; k < PP3; ++k) {
            if (U3[base + g * PP3 + k] != 0.f) {
                int a = w, b = x2, c = i;
                sort3(a, b, c);
                used3[a * 256 + b * 16 + c] = 1;
            }
        }
    }
    __syncthreads();

    // pair-even slotting: pair (a,b) with a<=b owns even # of slots
    int a = t >> 4, b = t & 15;
    int cnt = 0;
    if (t < 256 && a <= b)
        for (int c = b; c < 16; ++c) cnt += used3[a * 256 + b * 16 + c];
    int slots = (cnt + 1) & ~1;
    int total;
    int basep = block_exscan_1024((t < 256) ? slots : 0, t, warp_sums, &total);
    if (t < 256 && cnt > 0) {
        int pos = basep;
        for (int c = b; c < 16; ++c) {
            const int cell = a * 256 + b * 16 + c;
            if (used3[cell]) {
                g_cellid[cell] = (unsigned short)pos;
                g_spec[pos] = (uint32_t)a | ((uint32_t)b << 8) | ((uint32_t)c << 16);
                ++pos;
            }
        }
        if (cnt & 1)   // dummy slot: same (a,b), A row stays zero
            g_spec[pos] = (uint32_t)a | ((uint32_t)b << 8) | (15u << 16);
    }
    if (t == 0) g_K = (unsigned)((total + 15) & ~15);

    // ---- U2 list ----
    int cnt2 = 0;
    if (t < 256) {
#pragma unroll
        for (int k = 0; k < PP2; ++k) cnt2 += (U2[t * PP2 + k] != 0.f);
    }
    int total2;
    int p2 = block_exscan_1024(cnt2, t, warp_sums, &total2);
    if (t < 256) {
        const uint32_t wx = (uint32_t)(t >> 4) | ((uint32_t)(t & 15) << 8);
        for (int k = 0; k < PP2; ++k) {
            float v = U2[t * PP2 + k];
            if (v != 0.f) {
                g_e2[p2] = make_uint2(wx | ((uint32_t)k << 16), __float_as_uint(v));
                ++p2;
            }
        }
    }
    if (t == 0) g_n2 = (unsigned)total2;
}

// b1: zero A accumulator (grid-wide)
__global__ void build_b1()
{
    int i = blockIdx.x * blockDim.x + threadIdx.x;
    if (i < MAXK * NPAD) (&g_Af[0][0])[i] = 0.f;
}

// b2: accumulate A (grid-wide, one thread per U3 element)
__global__ void build_b2(const float* __restrict__ U3)
{
    int i = blockIdx.x * blockDim.x + threadIdx.x;
    if (i >= NU3) return;
    float v = U3[i];
    if (v == 0.f) return;
    int k = i % PP3;
    int r = i / PP3;
    int a = r >> 8, b = (r >> 4) & 15, c = r & 15;
    sort3(a, b, c);
    atomicAdd(&g_Af[g_cellid[a * 256 + b * 16 + c]][k], v);
}

// b3: convert to transposed fp16 (grid-wide)
__global__ void build_b3()
{
    int i = blockIdx.x * blockDim.x + threadIdx.x;
    if (i >= NPAD * MAXK) return;
    int n = i / MAXK, m = i % MAXK;
    g_AhT[n][m] = __float2half(g_Af[m][n]);
}

// ---------------------------------------------------------------------------
#define MMA16816(d0,d1,d2,d3,a0,a1,a2,a3,b0,b1)                         \
    asm volatile("mma.sync.aligned.m16n8k16.row.col.f32.f16.f16.f32 "   \
        "{%0,%1,%2,%3}, {%4,%5,%6,%7}, {%8,%9}, {%0,%1,%2,%3};"         \
        : "+f"(d0), "+f"(d1), "+f"(d2), "+f"(d3)                        \
        : "r"(a0), "r"(a1), "r"(a2), "r"(a3), "r"(b0), "r"(b1))

__device__ __forceinline__ __half2 u2h2(uint32_t u) { return *reinterpret_cast<__half2*>(&u); }
__device__ __forceinline__ uint32_t h2u(__half2 h) { return *reinterpret_cast<uint32_t*>(&h); }

// ---------------------------------------------------------------------------
// smem layout (bytes), block = 3 nodes x 128 threads
// X stored paired: row l = 64 half2 entries; entry e=8q+r holds
// half2( x[ch=16q+r], x[ch=16q+r+8] )  -> one LDS.32 = both fragment rows.
// ---------------------------------------------------------------------------
#define AHT_ROW   1936                        // 1920 data + 16 pad
#define OFF_AHT   0
#define OFF_SPEC  (NPAD * AHT_ROW)            // 46464
#define OFF_NODE  (OFF_SPEC + MAXK * 4)       // 50304
#define XH_ROW    272                         // 64 half2 (256B) + 16 pad
#define W3H_ROW   264                         // 128 fp16 + 8 pad
#define NB_XH     0
#define NB_W3     (NB_XH + LL * XH_ROW)       // 4352
#define NB_W2     (NB_W3 + NPAD * W3H_ROW)    // 10688
#define NB_W1     (NB_W2 + PP2 * 256)         // 11712
#define NB_OUT    (NB_W1 + 512)               // 12224
#define NODE_BYTES (NB_OUT + 512)             // 12736
#define SH_BYTES  (OFF_NODE + NNODES * NODE_BYTES)  // 88512

__global__ __launch_bounds__(THREADS, 2)
void sym_gemm_kernel(const float* __restrict__ x,
                     const float* __restrict__ y,
                     const float* __restrict__ w3,
                     const float* __restrict__ w2,
                     const float* __restrict__ w1,
                     const float* __restrict__ U1,
                     float* __restrict__ out,
                     int B)
{
    extern __shared__ char sm[];
    const int tid  = threadIdx.x;
    const int node = tid >> 7;
    const int wt   = tid & 127;               // channel for setup phases
    const int b    = blockIdx.x * NNODES + node;
    const bool valid = (b < B);

    char* nb  = sm + OFF_NODE + node * NODE_BYTES;
    char* xh  = nb + NB_XH;
    char* w3h = nb + NB_W3;
    char* w2h = nb + NB_W2;
    float* w1f  = reinterpret_cast<float*>(nb + NB_W1);
    float* outs = reinterpret_cast<float*>(nb + NB_OUT);

    const int KP = (int)g_K;
    const int n2 = (int)g_n2;

    // ---- copy AhT + spec into smem (all threads) ----
    for (int idx = tid; idx < NPAD * 120; idx += THREADS) {
        const int r = idx / 120, j = idx % 120;
        *reinterpret_cast<uint4*>(sm + OFF_AHT + r * AHT_ROW + j * 16) =
            *reinterpret_cast<const uint4*>(reinterpret_cast<const char*>(&g_AhT[0][0]) + r * (MAXK * 2) + j * 16);
    }
    for (int idx = tid; idx < MAXK; idx += THREADS)
        *reinterpret_cast<uint32_t*>(sm + OFF_SPEC + idx * 4) = g_spec[idx];

    // ---- stage x as PAIRED fp16: entry e = 8*(wt>>4)+(wt&7), half h = (wt>>3)&1
    const int xe = 8 * (wt >> 4) + (wt & 7);
    const int xho = (wt >> 3) & 1;
    if (valid) {
        const float4* xp = reinterpret_cast<const float4*>(x + ((size_t)b * CC + wt) * LL);
#pragma unroll
        for (int q = 0; q < 4; ++q) {
            float4 r = xp[q];
            *reinterpret_cast<__half*>(xh + (4 * q + 0) * XH_ROW + xe * 4 + xho * 2) = __float2half(r.x);
            *reinterpret_cast<__half*>(xh + (4 * q + 1) * XH_ROW + xe * 4 + xho * 2) = __float2half(r.y);
            *reinterpret_cast<__half*>(xh + (4 * q + 2) * XH_ROW + xe * 4 + xho * 2) = __float2half(r.z);
            *reinterpret_cast<__half*>(xh + (4 * q + 3) * XH_ROW + xe * 4 + xho * 2) = __float2half(r.w);
        }
    } else {
#pragma unroll
        for (int l = 0; l < LL; ++l)
            *reinterpret_cast<__half*>(xh + l * XH_ROW + xe * 4 + xho * 2) = __float2half(0.f);
    }

    // ---- effective weights ----
    float yr[EE];
#pragma unroll
    for (int e = 0; e < EE; ++e) yr[e] = valid ? __ldg(y + (size_t)b * EE + e) : 0.f;

#pragma unroll
    for (int k = 0; k < PP3; ++k) {
        float s = 0.f;
#pragma unroll
        for (int e = 0; e < EE; ++e)
            s = fmaf(yr[e], __ldg(w3 + (size_t)(e * PP3 + k) * CC + wt), s);
        *reinterpret_cast<__half*>(w3h + k * W3H_ROW + wt * 2) = __float2half(s);
    }
    *reinterpret_cast<__half*>(w3h + 23 * W3H_ROW + wt * 2) = __float2half(0.f);  // pad col
#pragma unroll
    for (int k = 0; k < PP2; ++k) {
        float s = 0.f;
#pragma unroll
        for (int e = 0; e < EE; ++e)
            s = fmaf(yr[e], __ldg(w2 + (size_t)(e * PP2 + k) * CC + wt), s);
        *reinterpret_cast<__half*>(w2h + k * 256 + wt * 2) = __float2half(s);
    }
    {
        float s = 0.f;
#pragma unroll
        for (int e = 0; e < EE; ++e)
            s = fmaf(yr[e], __ldg(w1 + (size_t)e * CC + wt), s);
        w1f[wt] = s;
    }
    __syncthreads();   // x (written by other threads' channels) + tables ready

    // ---- U2 + U1 scalar terms for channel wt ----
    {
        float o = 0.f;
        for (int e = 0; e < n2; ++e) {
            uint2 E = __ldg(&g_e2[e]);
            const int ww = E.x & 255, xx = (E.x >> 8) & 255, kk = E.x >> 16;
            float xw = __half2float(*reinterpret_cast<const __half*>(xh + ww * XH_ROW + xe * 4 + xho * 2))
                     * __half2float(*reinterpret_cast<const __half*>(xh + xx * XH_ROW + xe * 4 + xho * 2));
            float wv = __half2float(*reinterpret_cast<const __half*>(w2h + kk * 256 + wt * 2));
            o = fmaf(__uint_as_float(E.y) * wv, xw, o);
        }
        float d = 0.f;
#pragma unroll
        for (int l = 0; l < LL; ++l)
            d = fmaf(__ldg(U1 + l),
                     __half2float(*reinterpret_cast<const __half*>(xh + l * XH_ROW + xe * 4 + xho * 2)), d);
        o = fmaf(w1f[wt], d, o);
        outs[wt] = o;
    }

    // ---- GEMM main loop: fully barrier-free ----
    const int lane = tid & 31;
    const int wm   = (tid >> 5) & 3;          // warp within node
    const int g4   = lane >> 2;
    const int t4   = lane & 3;

    // per-lane x column base for each m-tile: entry = 8*(2*wm+mt) + g4
    const char* xc0 = xh + (8 * (2 * wm + 0) + g4) * 4;
    const char* xc1 = xh + (8 * (2 * wm + 1) + g4) * 4;
    const uint2* spec2 = reinterpret_cast<const uint2*>(sm + OFF_SPEC);
    const char* bb = sm + OFF_AHT + g4 * AHT_ROW + t4 * 4;

    float acc[2][3][4];
#pragma unroll
    for (int mt = 0; mt < 2; ++mt)
#pragma unroll
        for (int nt = 0; nt < 3; ++nt)
#pragma unroll
            for (int q = 0; q < 4; ++q) acc[mt][nt][q] = 0.f;

    const int nchunks = KP >> 4;
    for (int c = 0; c < nchunks; ++c) {
        const int kb = c * 16;
        // spec pairs for cols (2t4, 2t4+1) and (2t4+8, 2t4+9)
        uint2 spJ0 = spec2[(kb >> 1) + t4];
        uint2 spJ1 = spec2[(kb >> 1) + t4 + 4];

        uint32_t afr[2][4];
#pragma unroll
        for (int mt = 0; mt < 2; ++mt) {
            const char* xc = mt ? xc1 : xc0;
#pragma unroll
            for (int j = 0; j < 2; ++j) {
                const uint32_t spA = j ? spJ1.x : spJ0.x;
                const uint32_t spB = j ? spJ1.y : spJ0.y;
                __half2 xa = u2h2(*reinterpret_cast<const uint32_t*>(xc + (spA & 255u) * XH_ROW));
                __half2 xb = u2h2(*reinterpret_cast<const uint32_t*>(xc + ((spA >> 8) & 255u) * XH_ROW));
                __half2 c0 = u2h2(*reinterpret_cast<const uint32_t*>(xc + ((spA >> 16) & 255u) * XH_ROW));
                __half2 c1 = u2h2(*reinterpret_cast<const uint32_t*>(xc + ((spB >> 16) & 255u) * XH_ROW));
                __half2 ab = __hmul2(xa, xb);
                uint32_t p0 = h2u(__hmul2(ab, c0));   // (row g4, row g4+8) @ col k0
                uint32_t p1 = h2u(__hmul2(ab, c1));   // (row g4, row g4+8) @ col k1
                afr[mt][2 * j + 0] = __byte_perm(p0, p1, 0x5410);  // row g4:   (k0,k1)
                afr[mt][2 * j + 1] = __byte_perm(p0, p1, 0x7632);  // row g4+8: (k0,k1)
            }
        }

        // B fragments + mma
#pragma unroll
        for (int nt = 0; nt < 3; ++nt) {
            const char* bp = bb + nt * (8 * AHT_ROW) + kb * 2;
            uint32_t b0 = *reinterpret_cast<const uint32_t*>(bp);
            uint32_t b1 = *reinterpret_cast<const uint32_t*>(bp + 16);
            MMA16816(acc[0][nt][0], acc[0][nt][1], acc[0][nt][2], acc[0][nt][3],
                     afr[0][0], afr[0][1], afr[0][2], afr[0][3], b0, b1);
            MMA16816(acc[1][nt][0], acc[1][nt][1], acc[1][nt][2], acc[1][nt][3],
                     afr[1][0], afr[1][1], afr[1][2], afr[1][3], b0, b1);
        }
    }

    // ---- epilogue: out[ch] = outs[ch] + sum_k W3[k][ch] * Q[ch][k] ----
#pragma unroll
    for (int mt = 0; mt < 2; ++mt) {
#pragma unroll
        for (int h = 0; h < 2; ++h) {
            const int ch = wm * 32 + mt * 16 + g4 + h * 8;
            float S = 0.f;
#pragma unroll
            for (int nt = 0; nt < 3; ++nt) {
                const int k0 = nt * 8 + 2 * t4;
                float wv0 = __half2float(*reinterpret_cast<const __half*>(w3h + k0 * W3H_ROW + ch * 2));
                float wv1 = __half2float(*reinterpret_cast<const __half*>(w3h + (k0 + 1) * W3H_ROW + ch * 2));
                S = fmaf(acc[mt][nt][h * 2 + 0], wv0, S);
                S = fmaf(acc[mt][nt][h * 2 + 1], wv1, S);
            }
            S += __shfl_xor_sync(0xffffffffu, S, 1);
            S += __shfl_xor_sync(0xffffffffu, S, 2);
            if (t4 == 0 && valid)
                out[(size_t)b * CC + ch] = S + outs[ch];
        }
    }
}

// ---------------------------------------------------------------------------
extern "C" void kernel_launch(void* const* d_in, const int* in_sizes, int n_in,
                              void* d_out, int out_size)
{
    const float* x  = (const float*)d_in[0];   // [B,C,L]
    const float* y  = (const float*)d_in[1];   // [B,E]
    const float* U3 = (const float*)d_in[2];   // [16,16,16,23]
    const float* U2 = (const float*)d_in[3];   // [16,16,4]
    const float* U1 = (const float*)d_in[4];   // [16,1]
    const float* w3 = (const float*)d_in[5];   // [10,23,128]
    const float* w2 = (const float*)d_in[6];   // [10,4,128]
    const float* w1 = (const float*)d_in[7];   // [10,1,128]
    float* out = (float*)d_out;

    const int B = in_sizes[0] / (CC * LL);

    build_b0<<<1, 1024>>>(U3, U2);
    build_b1<<<(MAXK * NPAD + 255) / 256, 256>>>();
    build_b2<<<(NU3 + 255) / 256, 256>>>(U3);
    build_b3<<<(NPAD * MAXK + 255) / 256, 256>>>();

    cudaFuncSetAttribute(sym_gemm_kernel,
                         cudaFuncAttributeMaxDynamicSharedMemorySize, SH_BYTES);
    const int grid = (B + NNODES - 1) / NNODES;
    sym_gemm_kernel<<<grid, THREADS, SH_BYTES>>>(x, y, w3, w2, w1, U1, out, B);
}